// round 10
// baseline (speedup 1.0000x reference)
#include <cuda_runtime.h>
#include <cuda_fp16.h>
#include <math.h>
#include <stdint.h>

#define BB   8
#define SS   1024
#define DD   1024
#define HH   16
#define DKK  64
#define DF   4096
#define NTOK (BB*SS)        // 8192 tokens

// ---------------- scratch (static device globals; no allocation) ------------
__device__ __half g_xq[NTOK*DD];       // LN output (half), both LNs
__device__ __half g_xr[NTOK*DD];       // x as half
__device__ __half g_q [NTOK*DD];
__device__ __half g_kv[NTOK*2048];     // fused K|V: [token][0:1024)=k, [1024:2048)=v
__device__ __half g_vt[NTOK*DD];       // [b,h][dk][token] transposed V
__device__ __half g_ctx[NTOK*DD];
__device__ float  g_x1[NTOK*DD];       // after bn1 (exact fp32)
__device__ __half g_h [NTOK*DF];       // FFN hidden
__device__ __half g_w [12*1024*1024];  // half weights: Wq Wk Wv Wo | W1 | W2
__device__ __half g_ah[134217728];     // attn as half (B*H*S*S) for AV GEMM

// ---------------- helpers ----------------------------------------------------
__device__ __forceinline__ void cpa16(void* s, const void* g) {
    unsigned sa = (unsigned)__cvta_generic_to_shared(s);
    asm volatile("cp.async.cg.shared.global [%0], [%1], 16;" :: "r"(sa), "l"(g));
}
__device__ __forceinline__ void cpa16u(uint32_t sa, const void* g) {
    asm volatile("cp.async.cg.shared.global [%0], [%1], 16;" :: "r"(sa), "l"(g));
}
__device__ __forceinline__ void cp_commit() { asm volatile("cp.async.commit_group;"); }
template<int N> __device__ __forceinline__ void cp_wait() {
    asm volatile("cp.async.wait_group %0;" :: "n"(N));
}
__device__ __forceinline__ void mma16(float* c, const unsigned* a, const unsigned* b) {
    asm volatile(
        "mma.sync.aligned.m16n8k16.row.col.f32.f16.f16.f32 "
        "{%0,%1,%2,%3}, {%4,%5,%6,%7}, {%8,%9}, {%0,%1,%2,%3};"
        : "+f"(c[0]), "+f"(c[1]), "+f"(c[2]), "+f"(c[3])
        : "r"(a[0]), "r"(a[1]), "r"(a[2]), "r"(a[3]), "r"(b[0]), "r"(b[1]));
}
__device__ __forceinline__ void ldm4(unsigned* r, uint32_t addr) {
    asm volatile("ldmatrix.sync.aligned.m8n8.x4.shared.b16 {%0,%1,%2,%3}, [%4];"
                 : "=r"(r[0]), "=r"(r[1]), "=r"(r[2]), "=r"(r[3]) : "r"(addr));
}

// ---------------- fp16 tensor-core GEMM (ST-stage cp.async + ldmatrix, NT) ---
// C[M,N] = A[M,K] * B[N,K]^T + epilogue. A,B half, K-major.
// bias2: if non-null, cols >=1024 use bias2[n-1024] (fused KV projection).
// MODE: 0 bias | 1 bias+res+BN | 2 bias+GELU+BN | 4 raw
template<int BM,int BN,int WM,int WN,int ST,int MODE,bool OUTH>
__global__ void __launch_bounds__(256)
gemm_h(const __half* __restrict__ A, int lda, long aS1, long aS2,
       const __half* __restrict__ B, int ldb, long bS1, long bS2,
       void* __restrict__ Cv, int ldc, long cS1, long cS2,
       int K,
       const float* __restrict__ bias, const float* __restrict__ bias2,
       const float* __restrict__ res, int ldres,
       const float* __restrict__ bng, const float* __restrict__ bnb,
       const float* __restrict__ bnm, const float* __restrict__ bnv)
{
    constexpr int BK  = 32;              // k per stage (2 slabs of 16)
    constexpr int ASZ = BM * 80;         // bytes/stage (row stride 40 halves)
    constexpr int BSZ = BN * 80;

    extern __shared__ char smem[];
    const uint32_t smem_u = (uint32_t)__cvta_generic_to_shared(smem);

    const int z  = blockIdx.z;
    const int zb = z >> 4;
    const int zh = z & 15;
    A += (long)zb * aS1 + (long)zh * aS2;
    B += (long)zb * bS1 + (long)zh * bS2;

    const int tid = threadIdx.x;
    const int m0  = blockIdx.y * BM;
    const int n0  = blockIdx.x * BN;

    const int warp = tid >> 5, lane = tid & 31;
    constexpr int WGN = BN / WN;
    const int wm = warp / WGN, wn = warp % WGN;
    const int g  = lane >> 2,  t  = lane & 3;
    constexpr int MT  = WM / 16;
    constexpr int NTL = WN / 8;

    const int arow  = (lane & 7) | (((lane >> 3) & 1) << 3);
    const int akofs = (lane >> 4) << 3;
    const int brow  = ((lane >> 4) << 3) | (lane & 7);
    const int bkofs = ((lane >> 3) & 1) << 3;
    uint32_t aoff[MT], boff[NTL/2];
    #pragma unroll
    for (int mt = 0; mt < MT; mt++)
        aoff[mt] = ((wm * WM + mt * 16 + arow) * 40 + akofs) * 2;
    #pragma unroll
    for (int p = 0; p < NTL/2; p++)
        boff[p] = ((wn * WN + p * 16 + brow) * 40 + bkofs) * 2;

    float c[MT][NTL][4];
    #pragma unroll
    for (int i = 0; i < MT; i++)
        #pragma unroll
        for (int j = 0; j < NTL; j++)
            #pragma unroll
            for (int e = 0; e < 4; e++) c[i][j][e] = 0.0f;

    const int iters = K / BK;

    auto load_stage = [&](int it, int buf) {
        const int k0 = it * BK;
        char* dA = smem + buf * ASZ;
        char* dB = smem + ST * ASZ + buf * BSZ;
        #pragma unroll
        for (int s = tid; s < BM * 4; s += 256) {
            int row = s >> 2, seg = s & 3;
            cpa16(dA + row * 80 + seg * 16,
                  A + (long)(m0 + row) * lda + k0 + seg * 8);
        }
        #pragma unroll
        for (int s = tid; s < BN * 4; s += 256) {
            int row = s >> 2, seg = s & 3;
            cpa16(dB + row * 80 + seg * 16,
                  B + (long)(n0 + row) * ldb + k0 + seg * 8);
        }
    };

    #pragma unroll
    for (int s = 0; s < ST - 1; s++) {
        if (s < iters) load_stage(s, s);
        cp_commit();
    }

    for (int it = 0; it < iters; ++it) {
        cp_wait<ST - 2>();
        __syncthreads();

        if (it + ST - 1 < iters) load_stage(it + ST - 1, (it + ST - 1) % ST);
        cp_commit();

        const int buf = it % ST;
        const uint32_t aBase = smem_u + buf * ASZ;
        const uint32_t bBase = smem_u + ST * ASZ + buf * BSZ;

        #pragma unroll
        for (int ks = 0; ks < BK; ks += 16) {
            unsigned a[MT][4], b[NTL/2][4];
            #pragma unroll
            for (int mt = 0; mt < MT; mt++)
                ldm4(a[mt], aBase + aoff[mt] + ks * 2);
            #pragma unroll
            for (int p = 0; p < NTL/2; p++)
                ldm4(b[p], bBase + boff[p] + ks * 2);
            #pragma unroll
            for (int mt = 0; mt < MT; mt++)
                #pragma unroll
                for (int p = 0; p < NTL/2; p++) {
                    mma16(c[mt][2*p],   a[mt], &b[p][0]);
                    mma16(c[mt][2*p+1], a[mt], &b[p][2]);
                }
        }
    }

    auto ep = [&](float v, int n, long m) -> float {
        if constexpr (MODE == 0) {
            v += (bias2 && n >= 1024) ? bias2[n - 1024] : bias[n];
        } else if constexpr (MODE == 1) {
            v += bias[n] + res[m * ldres + n];
            v = (v - bnm[n]) * rsqrtf(bnv[n] + 1e-5f) * bng[n] + bnb[n];
        } else if constexpr (MODE == 2) {
            v += bias[n];
            v = 0.5f * v * (1.0f + erff(v * 0.70710678118654752f));
            v = (v - bnm[n]) * rsqrtf(bnv[n] + 1e-5f) * bng[n] + bnb[n];
        }
        return v;
    };

    const long cofs = (long)zb * cS1 + (long)zh * cS2;
    #pragma unroll
    for (int mt = 0; mt < MT; mt++) {
        #pragma unroll
        for (int nt = 0; nt < NTL; nt++) {
            const int row = m0 + wm * WM + mt * 16 + g;
            const int col = n0 + wn * WN + nt * 8 + 2 * t;
            float v00 = ep(c[mt][nt][0], col,     row);
            float v01 = ep(c[mt][nt][1], col + 1, row);
            float v10 = ep(c[mt][nt][2], col,     row + 8);
            float v11 = ep(c[mt][nt][3], col + 1, row + 8);
            if constexpr (OUTH) {
                __half* Ch = (__half*)Cv + cofs;
                *(__half2*)(Ch + (long)(row    ) * ldc + col) = __floats2half2_rn(v00, v01);
                *(__half2*)(Ch + (long)(row + 8) * ldc + col) = __floats2half2_rn(v10, v11);
            } else {
                float* Cf = (float*)Cv + cofs;
                *(float2*)(Cf + (long)(row    ) * ldc + col) = make_float2(v00, v01);
                *(float2*)(Cf + (long)(row + 8) * ldc + col) = make_float2(v10, v11);
            }
        }
    }
}

// ---------------- fused scores + mask + softmax ------------------------------
// One block: 32-row strip x full S=1024 cols for one (b,h).
// Phase 1: scores = q k^T/8 (+mask) chunk-by-chunk into fp32 smem.
// Phase 2: row softmax in smem; write final attn fp32 (d_out) + half (ah).
__global__ void __launch_bounds__(256)
sf_k(const __half* __restrict__ q,    // [NTOK, DD], head col = zh*64
     const __half* __restrict__ kv,   // [NTOK, 2048], k at col zh*64
     float* __restrict__ outa,        // [B,H,S,S]
     __half* __restrict__ ah,         // [B,H,S,S] half
     const int* __restrict__ mask)    // [B,1,1,S]
{
    constexpr int ROWS = 32;
    constexpr int SSTR = 1028;             // fp32 scores row stride
    constexpr int QSZ  = ROWS * 144;       // 72-half rows
    constexpr int KSZ  = 128 * 144;
    constexpr int SOFS = ROWS * SSTR * 4;  // 131584

    extern __shared__ char smem[];
    const uint32_t smem_u = (uint32_t)__cvta_generic_to_shared(smem);
    float* sS = (float*)smem;
    const uint32_t qBase = smem_u + SOFS;
    const uint32_t kBase = smem_u + SOFS + QSZ;

    const int z  = blockIdx.z;             // b*16 + h
    const int zb = z >> 4;
    const int zh = z & 15;
    const int m0 = blockIdx.x * ROWS;

    const int tid = threadIdx.x;
    const int warp = tid >> 5, lane = tid & 31;
    const int wm = warp >> 2, wn = warp & 3;   // 2 x 4 warps, WM=16, WN=32
    const int g  = lane >> 2,  t = lane & 3;

    const int arow  = (lane & 7) | (((lane >> 3) & 1) << 3);
    const int akofs = (lane >> 4) << 3;
    const int brow  = ((lane >> 4) << 3) | (lane & 7);
    const int bkofs = ((lane >> 3) & 1) << 3;
    const uint32_t aoff = ((wm * 16 + arow) * 72 + akofs) * 2;
    uint32_t boff[2];
    #pragma unroll
    for (int p = 0; p < 2; p++)
        boff[p] = ((wn * 32 + p * 16 + brow) * 72 + bkofs) * 2;

    auto load_q = [&] {
        int row = tid >> 3, seg = tid & 7;
        cpa16u(qBase + row * 144 + seg * 16,
               q + (long)(zb * SS + m0 + row) * DD + zh * 64 + seg * 8);
    };
    auto load_k = [&](int nc, int buf) {
        #pragma unroll
        for (int s = tid; s < 1024; s += 256) {
            int row = s >> 3, seg = s & 7;
            cpa16u(kBase + buf * KSZ + row * 144 + seg * 16,
                   kv + (long)(zb * SS + nc * 128 + row) * 2048 + zh * 64 + seg * 8);
        }
    };

    load_q(); load_k(0, 0); cp_commit();
    load_k(1, 1); cp_commit();

    for (int nc = 0; nc < 8; ++nc) {
        cp_wait<1>();
        __syncthreads();
        if (nc + 2 < 8) load_k(nc + 2, (nc + 2) % 3);
        cp_commit();

        const uint32_t kb = kBase + (nc % 3) * KSZ;
        float c[4][4];
        #pragma unroll
        for (int i = 0; i < 4; i++)
            #pragma unroll
            for (int e = 0; e < 4; e++) c[i][e] = 0.0f;

        #pragma unroll
        for (int ks = 0; ks < 64; ks += 16) {
            unsigned a[4], b0[4], b1[4];
            ldm4(a,  qBase + aoff + ks * 2);
            ldm4(b0, kb + boff[0] + ks * 2);
            ldm4(b1, kb + boff[1] + ks * 2);
            mma16(c[0], a, &b0[0]);
            mma16(c[1], a, &b0[2]);
            mma16(c[2], a, &b1[0]);
            mma16(c[3], a, &b1[2]);
        }

        // store chunk to smem scores with mask + scale
        #pragma unroll
        for (int nt = 0; nt < 4; nt++) {
            const int row = wm * 16 + g;
            const int col = nc * 128 + wn * 32 + nt * 8 + 2 * t;
            const int mA = mask[zb * SS + col];
            const int mB = mask[zb * SS + col + 1];
            float s00 = mA ? c[nt][0] * 0.125f : -1e9f;
            float s01 = mB ? c[nt][1] * 0.125f : -1e9f;
            float s10 = mA ? c[nt][2] * 0.125f : -1e9f;
            float s11 = mB ? c[nt][3] * 0.125f : -1e9f;
            *(float2*)&sS[(row    ) * SSTR + col] = make_float2(s00, s01);
            *(float2*)&sS[(row + 8) * SSTR + col] = make_float2(s10, s11);
        }
    }
    __syncthreads();

    // ---- phase 2: row softmax; warp handles 4 rows ----
    #pragma unroll
    for (int r = 0; r < 4; r++) {
        const int row = warp * 4 + r;
        float* srow = sS + row * SSTR;

        float mx = -1e30f;
        #pragma unroll
        for (int it = 0; it < 8; it++) {
            float4 v = *(float4*)&srow[it * 128 + lane * 4];
            mx = fmaxf(mx, fmaxf(fmaxf(v.x, v.y), fmaxf(v.z, v.w)));
        }
        #pragma unroll
        for (int o = 16; o; o >>= 1)
            mx = fmaxf(mx, __shfl_xor_sync(0xffffffffu, mx, o));

        float sum = 0.0f;
        #pragma unroll
        for (int it = 0; it < 8; it++) {
            float4 v = *(float4*)&srow[it * 128 + lane * 4];
            v.x = __expf(v.x - mx); v.y = __expf(v.y - mx);
            v.z = __expf(v.z - mx); v.w = __expf(v.w - mx);
            *(float4*)&srow[it * 128 + lane * 4] = v;
            sum += v.x + v.y + v.z + v.w;
        }
        #pragma unroll
        for (int o = 16; o; o >>= 1)
            sum += __shfl_xor_sync(0xffffffffu, sum, o);
        const float inv = 1.0f / sum;

        const long base = (long)z * SS * SS + (long)(m0 + row) * SS;
        #pragma unroll
        for (int it = 0; it < 8; it++) {
            const int col = it * 128 + lane * 4;
            float4 v = *(float4*)&srow[col];
            v.x *= inv; v.y *= inv; v.z *= inv; v.w *= inv;
            *(float4*)&outa[base + col] = v;
            *(__half2*)(ah + base + col)     = __floats2half2_rn(v.x, v.y);
            *(__half2*)(ah + base + col + 2) = __floats2half2_rn(v.z, v.w);
        }
    }
}

// ---------------- float -> half convert (vectorized) -------------------------
__global__ void __launch_bounds__(256)
cvt_k(const float* __restrict__ in, __half* __restrict__ out, int n4)
{
    int i = blockIdx.x * 256 + threadIdx.x;
    if (i < n4) {
        float4 v = ((const float4*)in)[i];
        ((__half2*)out)[2*i]   = __floats2half2_rn(v.x, v.y);
        ((__half2*)out)[2*i+1] = __floats2half2_rn(v.z, v.w);
    }
}

// ---------------- V transpose: kv[token][1024+h*64+dk] -> vt[b,h][dk][s] -----
__global__ void __launch_bounds__(256)
vt_k(const __half* __restrict__ v, int ldv, __half* __restrict__ vt)
{
    __shared__ __half tile[64][72];
    const int z = blockIdx.z;
    const int b = z >> 4, h = z & 15;
    const int s0 = blockIdx.x * 64;
    const int tid = threadIdx.x;

    #pragma unroll
    for (int p = 0; p < 2; p++) {
        int r   = p * 32 + (tid >> 3);
        int seg = tid & 7;
        uint4 d = *(const uint4*)(v + ((long)(b * SS + s0 + r)) * ldv + h * 64 + seg * 8);
        *(uint4*)&tile[r][seg * 8] = d;
    }
    __syncthreads();
    #pragma unroll
    for (int p = 0; p < 2; p++) {
        int c   = p * 32 + (tid >> 3);
        int seg = tid & 7;
        __half tmp[8];
        #pragma unroll
        for (int j = 0; j < 8; j++) tmp[j] = tile[seg * 8 + j][c];
        *(uint4*)(vt + ((long)z * 64 + c) * SS + s0 + seg * 8) = *(uint4*)tmp;
    }
}

// ---------------- LayerNorm over D=1024; half output -------------------------
__global__ void __launch_bounds__(256)
ln_k(const float* __restrict__ x, const float* __restrict__ g,
     const float* __restrict__ b, __half* __restrict__ o)
{
    __shared__ float red[8];
    const long row = blockIdx.x;
    const int  t = threadIdx.x, lane = t & 31, w = t >> 5;

    float4 v = ((const float4*)(x + row * DD))[t];
    float s = v.x + v.y + v.z + v.w;
    #pragma unroll
    for (int off = 16; off; off >>= 1) s += __shfl_down_sync(0xffffffffu, s, off);
    if (!lane) red[w] = s;
    __syncthreads();
    if (t == 0) { float a = 0.f; for (int i = 0; i < 8; i++) a += red[i]; red[0] = a; }
    __syncthreads();
    const float mu = red[0] * (1.0f / DD);
    __syncthreads();

    float d0 = v.x - mu, d1 = v.y - mu, d2 = v.z - mu, d3 = v.w - mu;
    float sq = d0*d0 + d1*d1 + d2*d2 + d3*d3;
    #pragma unroll
    for (int off = 16; off; off >>= 1) sq += __shfl_down_sync(0xffffffffu, sq, off);
    if (!lane) red[w] = sq;
    __syncthreads();
    if (t == 0) { float a = 0.f; for (int i = 0; i < 8; i++) a += red[i]; red[0] = a; }
    __syncthreads();
    const float rs = rsqrtf(red[0] * (1.0f / DD) + 1e-5f);

    float4 g4 = ((const float4*)g)[t];
    float4 b4 = ((const float4*)b)[t];
    __half2* op = (__half2*)(o + row * DD);
    op[2*t]   = __floats2half2_rn(d0 * rs * g4.x + b4.x, d1 * rs * g4.y + b4.y);
    op[2*t+1] = __floats2half2_rn(d2 * rs * g4.z + b4.z, d3 * rs * g4.w + b4.w);
}

// ---------------- host orchestration ----------------------------------------
extern "C" void kernel_launch(void* const* d_in, const int* in_sizes, int n_in,
                              void* d_out, int out_size)
{
    const float* x    = (const float*)d_in[0];
    const int*   mask = (const int*)  d_in[1];
    const float* Wq = (const float*)d_in[2];  const float* bq = (const float*)d_in[3];
    const float* Wk = (const float*)d_in[4];  const float* bk = (const float*)d_in[5];
    const float* Wv = (const float*)d_in[6];  const float* bv = (const float*)d_in[7];
    const float* Wo = (const float*)d_in[8];  const float* bo = (const float*)d_in[9];
    const float* lag = (const float*)d_in[10]; const float* lab = (const float*)d_in[11];
    const float* W1 = (const float*)d_in[12]; const float* b1 = (const float*)d_in[13];
    const float* W2 = (const float*)d_in[14]; const float* b2 = (const float*)d_in[15];
    const float* lfg = (const float*)d_in[16]; const float* lfb = (const float*)d_in[17];
    const float* bnffg = (const float*)d_in[18]; const float* bnffb = (const float*)d_in[19];
    const float* bnffm = (const float*)d_in[20]; const float* bnffv = (const float*)d_in[21];
    const float* bn1g = (const float*)d_in[22]; const float* bn1b = (const float*)d_in[23];
    const float* bn1m = (const float*)d_in[24]; const float* bn1v = (const float*)d_in[25];
    const float* bn2g = (const float*)d_in[26]; const float* bn2b = (const float*)d_in[27];
    const float* bn2m = (const float*)d_in[28]; const float* bn2v = (const float*)d_in[29];

    __half *xq, *xr, *q, *kv, *vt, *ctx, *h, *w, *ah;
    float *x1;
    cudaGetSymbolAddress((void**)&xq,  g_xq);
    cudaGetSymbolAddress((void**)&xr,  g_xr);
    cudaGetSymbolAddress((void**)&q,   g_q);
    cudaGetSymbolAddress((void**)&kv,  g_kv);
    cudaGetSymbolAddress((void**)&vt,  g_vt);
    cudaGetSymbolAddress((void**)&ctx, g_ctx);
    cudaGetSymbolAddress((void**)&x1,  g_x1);
    cudaGetSymbolAddress((void**)&h,   g_h);
    cudaGetSymbolAddress((void**)&w,   g_w);
    cudaGetSymbolAddress((void**)&ah,  g_ah);

    __half* cWq = w;
    __half* cWk = w + 1*1024*1024;     // cWk..cWv contiguous = fused KV weight
    __half* cWv = w + 2*1024*1024;
    __half* cWo = w + 3*1024*1024;
    __half* cW1 = w + 4*1024*1024;
    __half* cW2 = w + 8*1024*1024;

    float* outx = (float*)d_out;                    // [B,S,D]
    float* outa = outx + (long)NTOK * DD;           // [B,H,S,S]

    constexpr int SM_B  = 4 * (128*80 + 256*80);        // 122880 B (big NT GEMMs)
    constexpr int SM_AV = 3 * (128*80 +  64*80);        // 46080 B (attn@V)
    constexpr int SM_SF = 32*1028*4 + 32*144 + 3*128*144;  // 191488 B (fused scores+softmax)

    //                 BM  BN  WM WN ST  MODE OUTH
    auto* kP  = gemm_h<128,256,64,64,4,  0,   true >;  // q / kv -> half
    auto* kAV = gemm_h<128, 64,32,32,3,  4,   true >;  // attn_h @ Vt -> ctx half
    auto* kR  = gemm_h<128,256,64,64,4,  1,   false>;  // O-proj / W2 -> fp32
    auto* kG  = gemm_h<128,256,64,64,4,  2,   true >;  // W1 -> h half
    cudaFuncSetAttribute((const void*)kP,  cudaFuncAttributeMaxDynamicSharedMemorySize, SM_B);
    cudaFuncSetAttribute((const void*)kAV, cudaFuncAttributeMaxDynamicSharedMemorySize, SM_AV);
    cudaFuncSetAttribute((const void*)kR,  cudaFuncAttributeMaxDynamicSharedMemorySize, SM_B);
    cudaFuncSetAttribute((const void*)kG,  cudaFuncAttributeMaxDynamicSharedMemorySize, SM_B);
    cudaFuncSetAttribute((const void*)sf_k, cudaFuncAttributeMaxDynamicSharedMemorySize, SM_SF);

    // 0) convert weights + x to half
    cvt_k<<<(1024*1024/4 + 255)/256, 256>>>(Wq, cWq, 1024*1024/4);
    cvt_k<<<(1024*1024/4 + 255)/256, 256>>>(Wk, cWk, 1024*1024/4);
    cvt_k<<<(1024*1024/4 + 255)/256, 256>>>(Wv, cWv, 1024*1024/4);
    cvt_k<<<(1024*1024/4 + 255)/256, 256>>>(Wo, cWo, 1024*1024/4);
    cvt_k<<<(4*1024*1024/4 + 255)/256, 256>>>(W1, cW1, 4*1024*1024/4);
    cvt_k<<<(4*1024*1024/4 + 255)/256, 256>>>(W2, cW2, 4*1024*1024/4);
    cvt_k<<<(NTOK*DD/4 + 255)/256, 256>>>(x, xr, NTOK*DD/4);

    // 1) pre-LN for query path (half out)
    ln_k<<<NTOK, 256>>>(x, lag, lab, xq);

    // 2) q projection (N=1024) + fused kv projection (N=2048)
    dim3 gQ(DD / 256, NTOK / 128, 1);
    kP<<<gQ, 256, SM_B>>>(xq, DD,0,0, cWq, DD,0,0, q, DD,0,0, DD,
        bq, nullptr, nullptr,0, nullptr,nullptr,nullptr,nullptr);
    dim3 gKV(2048 / 256, NTOK / 128, 1);
    kP<<<gKV, 256, SM_B>>>(xr, DD,0,0, cWk, DD,0,0, kv, 2048,0,0, DD,
        bk, bv, nullptr,0, nullptr,nullptr,nullptr,nullptr);

    // 2b) transpose V part of kv: [s, dk] -> [dk, s] per (b,h)
    dim3 gV(SS / 64, 1, BB * HH);
    vt_k<<<gV, 256>>>(kv + 1024, 2048, vt);

    // 3+4) fused scores + mask + softmax -> attn fp32 (d_out) + half (ah)
    dim3 gSF(SS / 32, 1, BB * HH);
    sf_k<<<gSF, 256, SM_SF>>>(q, kv, outa, ah, mask);

    // 5) context = attn_h @ Vt  (all-half NT GEMM)
    dim3 gC(1, SS / 128, BB * HH);
    kAV<<<gC, 256, SM_AV>>>(
        ah,   SS, (long)HH * SS * SS, (long)SS * SS,
        vt,   SS, (long)HH * DKK * SS, (long)DKK * SS,
        ctx,  DD, (long)SS * DD, 64,
        SS, nullptr, nullptr, nullptr,0, nullptr,nullptr,nullptr,nullptr);

    // 6) O projection + residual(x) + bn1 -> x1 (fp32)
    dim3 gO(DD / 256, NTOK / 128, 1);
    kR<<<gO, 256, SM_B>>>(ctx, DD,0,0, cWo, DD,0,0, x1, DD,0,0, DD,
        bo, nullptr, x, DD, bn1g,bn1b,bn1m,bn1v);

    // 7) FFN pre-LN (half out)
    ln_k<<<NTOK, 256>>>(x1, lfg, lfb, xq);

    // 8) h = bnff(gelu(xn W1^T + b1)) -> half  M=8192 N=4096 K=1024
    dim3 g1(DF / 256, NTOK / 128, 1);
    kG<<<g1, 256, SM_B>>>(xq, DD,0,0, cW1, DD,0,0, h, DF,0,0, DD,
        b1, nullptr, nullptr,0, bnffg,bnffb,bnffm,bnffv);

    // 9) out_x = bn2(h W2^T + b2 + x1)  M=8192 N=1024 K=4096
    dim3 g2(DD / 256, NTOK / 128, 1);
    kR<<<g2, 256, SM_B>>>(h, DF,0,0, cW2, DF,0,0, outx, DD,0,0, DF,
        b2, nullptr, x1, DD, bn2g,bn2b,bn2m,bn2v);
}

// round 12
// speedup vs baseline: 1.0238x; 1.0238x over previous
#include <cuda_runtime.h>
#include <cuda_fp16.h>
#include <math.h>
#include <stdint.h>

#define BB   8
#define SS   1024
#define DD   1024
#define HH   16
#define DKK  64
#define DF   4096
#define NTOK (BB*SS)        // 8192 tokens

// ---------------- scratch (static device globals; no allocation) ------------
__device__ __half g_xq[NTOK*DD];       // LN output (half), both LNs
__device__ __half g_xr[NTOK*DD];       // x as half
__device__ __half g_q [NTOK*DD];
__device__ __half g_kv[NTOK*2048];     // fused K|V: [token][0:1024)=k, [1024:2048)=v
__device__ __half g_vt[NTOK*DD];       // [b,h][dk][token] transposed V
__device__ __half g_ctx[NTOK*DD];
__device__ float  g_x1[NTOK*DD];       // after bn1 (exact fp32)
__device__ __half g_h [NTOK*DF];       // FFN hidden
__device__ __half g_w [12*1024*1024];  // half weights: Wq Wk Wv Wo | W1 | W2
__device__ __half g_ah[134217728];     // attn as half (B*H*S*S) for AV GEMM

// ---------------- helpers ----------------------------------------------------
__device__ __forceinline__ void cpa16(void* s, const void* g) {
    unsigned sa = (unsigned)__cvta_generic_to_shared(s);
    asm volatile("cp.async.cg.shared.global [%0], [%1], 16;" :: "r"(sa), "l"(g));
}
__device__ __forceinline__ void cpa16u(uint32_t sa, const void* g) {
    asm volatile("cp.async.cg.shared.global [%0], [%1], 16;" :: "r"(sa), "l"(g));
}
__device__ __forceinline__ void cp_commit() { asm volatile("cp.async.commit_group;"); }
template<int N> __device__ __forceinline__ void cp_wait() {
    asm volatile("cp.async.wait_group %0;" :: "n"(N));
}
__device__ __forceinline__ void mma16(float* c, const unsigned* a, const unsigned* b) {
    asm volatile(
        "mma.sync.aligned.m16n8k16.row.col.f32.f16.f16.f32 "
        "{%0,%1,%2,%3}, {%4,%5,%6,%7}, {%8,%9}, {%0,%1,%2,%3};"
        : "+f"(c[0]), "+f"(c[1]), "+f"(c[2]), "+f"(c[3])
        : "r"(a[0]), "r"(a[1]), "r"(a[2]), "r"(a[3]), "r"(b[0]), "r"(b[1]));
}
__device__ __forceinline__ void ldm4(unsigned* r, uint32_t addr) {
    asm volatile("ldmatrix.sync.aligned.m8n8.x4.shared.b16 {%0,%1,%2,%3}, [%4];"
                 : "=r"(r[0]), "=r"(r[1]), "=r"(r[2]), "=r"(r[3]) : "r"(addr));
}

// ---------------- fp16 tensor-core GEMM (ST-stage cp.async + ldmatrix, NT) ---
// C[M,N] = A[M,K] * B[N,K]^T + epilogue. A,B half, K-major.
// bias2: if non-null, cols >=1024 use bias2[n-1024] (fused KV projection).
// MODE: 0 bias | 1 bias+res+BN | 2 bias+GELU+BN | 4 raw
template<int BM,int BN,int WM,int WN,int ST,int MODE,bool OUTH>
__global__ void __launch_bounds__(256)
gemm_h(const __half* __restrict__ A, int lda, long aS1, long aS2,
       const __half* __restrict__ B, int ldb, long bS1, long bS2,
       void* __restrict__ Cv, int ldc, long cS1, long cS2,
       int K,
       const float* __restrict__ bias, const float* __restrict__ bias2,
       const float* __restrict__ res, int ldres,
       const float* __restrict__ bng, const float* __restrict__ bnb,
       const float* __restrict__ bnm, const float* __restrict__ bnv)
{
    constexpr int BK  = 32;
    constexpr int ASZ = BM * 80;
    constexpr int BSZ = BN * 80;

    extern __shared__ char smem[];
    const uint32_t smem_u = (uint32_t)__cvta_generic_to_shared(smem);

    const int z  = blockIdx.z;
    const int zb = z >> 4;
    const int zh = z & 15;
    A += (long)zb * aS1 + (long)zh * aS2;
    B += (long)zb * bS1 + (long)zh * bS2;

    const int tid = threadIdx.x;
    const int m0  = blockIdx.y * BM;
    const int n0  = blockIdx.x * BN;

    const int warp = tid >> 5, lane = tid & 31;
    constexpr int WGN = BN / WN;
    const int wm = warp / WGN, wn = warp % WGN;
    const int g  = lane >> 2,  t  = lane & 3;
    constexpr int MT  = WM / 16;
    constexpr int NTL = WN / 8;

    const int arow  = (lane & 7) | (((lane >> 3) & 1) << 3);
    const int akofs = (lane >> 4) << 3;
    const int brow  = ((lane >> 4) << 3) | (lane & 7);
    const int bkofs = ((lane >> 3) & 1) << 3;
    uint32_t aoff[MT], boff[NTL/2];
    #pragma unroll
    for (int mt = 0; mt < MT; mt++)
        aoff[mt] = ((wm * WM + mt * 16 + arow) * 40 + akofs) * 2;
    #pragma unroll
    for (int p = 0; p < NTL/2; p++)
        boff[p] = ((wn * WN + p * 16 + brow) * 40 + bkofs) * 2;

    float c[MT][NTL][4];
    #pragma unroll
    for (int i = 0; i < MT; i++)
        #pragma unroll
        for (int j = 0; j < NTL; j++)
            #pragma unroll
            for (int e = 0; e < 4; e++) c[i][j][e] = 0.0f;

    const int iters = K / BK;

    auto load_stage = [&](int it, int buf) {
        const int k0 = it * BK;
        char* dA = smem + buf * ASZ;
        char* dB = smem + ST * ASZ + buf * BSZ;
        #pragma unroll
        for (int s = tid; s < BM * 4; s += 256) {
            int row = s >> 2, seg = s & 3;
            cpa16(dA + row * 80 + seg * 16,
                  A + (long)(m0 + row) * lda + k0 + seg * 8);
        }
        #pragma unroll
        for (int s = tid; s < BN * 4; s += 256) {
            int row = s >> 2, seg = s & 3;
            cpa16(dB + row * 80 + seg * 16,
                  B + (long)(n0 + row) * ldb + k0 + seg * 8);
        }
    };

    #pragma unroll
    for (int s = 0; s < ST - 1; s++) {
        if (s < iters) load_stage(s, s);
        cp_commit();
    }

    for (int it = 0; it < iters; ++it) {
        cp_wait<ST - 2>();
        __syncthreads();

        if (it + ST - 1 < iters) load_stage(it + ST - 1, (it + ST - 1) % ST);
        cp_commit();

        const int buf = it % ST;
        const uint32_t aBase = smem_u + buf * ASZ;
        const uint32_t bBase = smem_u + ST * ASZ + buf * BSZ;

        #pragma unroll
        for (int ks = 0; ks < BK; ks += 16) {
            unsigned a[MT][4], b[NTL/2][4];
            #pragma unroll
            for (int mt = 0; mt < MT; mt++)
                ldm4(a[mt], aBase + aoff[mt] + ks * 2);
            #pragma unroll
            for (int p = 0; p < NTL/2; p++)
                ldm4(b[p], bBase + boff[p] + ks * 2);
            #pragma unroll
            for (int mt = 0; mt < MT; mt++)
                #pragma unroll
                for (int p = 0; p < NTL/2; p++) {
                    mma16(c[mt][2*p],   a[mt], &b[p][0]);
                    mma16(c[mt][2*p+1], a[mt], &b[p][2]);
                }
        }
    }

    auto ep = [&](float v, int n, long m) -> float {
        if constexpr (MODE == 0) {
            v += (bias2 && n >= 1024) ? bias2[n - 1024] : bias[n];
        } else if constexpr (MODE == 1) {
            v += bias[n] + res[m * ldres + n];
            v = (v - bnm[n]) * rsqrtf(bnv[n] + 1e-5f) * bng[n] + bnb[n];
        } else if constexpr (MODE == 2) {
            v += bias[n];
            v = 0.5f * v * (1.0f + erff(v * 0.70710678118654752f));
            v = (v - bnm[n]) * rsqrtf(bnv[n] + 1e-5f) * bng[n] + bnb[n];
        }
        return v;
    };

    const long cofs = (long)zb * cS1 + (long)zh * cS2;
    #pragma unroll
    for (int mt = 0; mt < MT; mt++) {
        #pragma unroll
        for (int nt = 0; nt < NTL; nt++) {
            const int row = m0 + wm * WM + mt * 16 + g;
            const int col = n0 + wn * WN + nt * 8 + 2 * t;
            float v00 = ep(c[mt][nt][0], col,     row);
            float v01 = ep(c[mt][nt][1], col + 1, row);
            float v10 = ep(c[mt][nt][2], col,     row + 8);
            float v11 = ep(c[mt][nt][3], col + 1, row + 8);
            if constexpr (OUTH) {
                __half* Ch = (__half*)Cv + cofs;
                *(__half2*)(Ch + (long)(row    ) * ldc + col) = __floats2half2_rn(v00, v01);
                *(__half2*)(Ch + (long)(row + 8) * ldc + col) = __floats2half2_rn(v10, v11);
            } else {
                float* Cf = (float*)Cv + cofs;
                *(float2*)(Cf + (long)(row    ) * ldc + col) = make_float2(v00, v01);
                *(float2*)(Cf + (long)(row + 8) * ldc + col) = make_float2(v10, v11);
            }
        }
    }
}

// ---------------- fused scores+mask+softmax, two-pass online (no scores buf) -
// Block: 32 query rows x one (b,h). Pass 1 (it 0-7): online row max/sum.
// Reduction across warps. Pass 2 (it 8-15): recompute scores, write final
// attn fp32 (d_out) + half (ah). K chunks stream through a 3-buffer ring
// continuously across both passes (pass-2 chunks are L2 hits).
__global__ void __launch_bounds__(256)
sf2_k(const __half* __restrict__ q,
      const __half* __restrict__ kv,
      float* __restrict__ outa,
      __half* __restrict__ ah,
      const int* __restrict__ mask)
{
    constexpr int ROWS = 32;
    constexpr int QSZ  = ROWS * 144;
    constexpr int KSZ  = 128 * 144;

    extern __shared__ char smem[];
    const uint32_t smem_u = (uint32_t)__cvta_generic_to_shared(smem);
    const uint32_t qBase = smem_u;
    const uint32_t kBase = smem_u + QSZ;
    float* sM  = (float*)(smem + QSZ + 3 * KSZ);   // [32][4]
    float* sSm = sM + 128;                          // [32][4]
    float* fM  = sSm + 128;                         // [32]
    float* fI  = fM + 32;                           // [32]

    const int z  = blockIdx.z;
    const int zb = z >> 4;
    const int zh = z & 15;
    const int m0r = blockIdx.x * ROWS;

    const int tid = threadIdx.x;
    const int warp = tid >> 5, lane = tid & 31;
    const int wm = warp >> 2, wn = warp & 3;        // 2 x 4 warps, WM=16, WN=32
    const int g  = lane >> 2,  t = lane & 3;

    const int arow  = (lane & 7) | (((lane >> 3) & 1) << 3);
    const int akofs = (lane >> 4) << 3;
    const int brow  = ((lane >> 4) << 3) | (lane & 7);
    const int bkofs = ((lane >> 3) & 1) << 3;
    const uint32_t aoff = ((wm * 16 + arow) * 72 + akofs) * 2;
    uint32_t boff[2];
    #pragma unroll
    for (int p = 0; p < 2; p++)
        boff[p] = ((wn * 32 + p * 16 + brow) * 72 + bkofs) * 2;

    auto load_q = [&] {
        int row = tid >> 3, seg = tid & 7;
        cpa16u(qBase + row * 144 + seg * 16,
               q + (long)(zb * SS + m0r + row) * DD + zh * 64 + seg * 8);
    };
    auto load_k = [&](int nc, int buf) {
        #pragma unroll
        for (int s = tid; s < 1024; s += 256) {
            int row = s >> 3, seg = s & 7;
            cpa16u(kBase + buf * KSZ + row * 144 + seg * 16,
                   kv + (long)(zb * SS + nc * 128 + row) * 2048 + zh * 64 + seg * 8);
        }
    };

    load_q(); load_k(0, 0); cp_commit();
    load_k(1, 1); cp_commit();

    float mrun0 = -1e30f, mrun1 = -1e30f, srun0 = 0.0f, srun1 = 0.0f;
    const long zbase = (long)z * SS * SS;

    for (int it = 0; it < 16; ++it) {
        const int nc = it & 7;
        cp_wait<1>();
        __syncthreads();
        if (it + 2 < 16) load_k((it + 2) & 7, (it + 2) % 3);
        cp_commit();

        // ---- cross-warp softmax stats reduction between passes ----
        if (it == 8) {
            if (t == 0) {
                const int r0 = wm * 16 + g;
                sM [r0 * 4 + wn] = mrun0;  sSm[r0 * 4 + wn] = srun0;
                sM [(r0+8) * 4 + wn] = mrun1;  sSm[(r0+8) * 4 + wn] = srun1;
            }
            __syncthreads();
            if (tid < 32) {
                float m = sM[tid*4];
                m = fmaxf(m, sM[tid*4+1]); m = fmaxf(m, sM[tid*4+2]); m = fmaxf(m, sM[tid*4+3]);
                float s = 0.0f;
                #pragma unroll
                for (int j = 0; j < 4; j++) s += sSm[tid*4+j] * __expf(sM[tid*4+j] - m);
                fM[tid] = m; fI[tid] = 1.0f / s;
            }
            __syncthreads();
        }

        const uint32_t kb = kBase + (it % 3) * KSZ;
        float c[4][4];
        #pragma unroll
        for (int i = 0; i < 4; i++)
            #pragma unroll
            for (int e = 0; e < 4; e++) c[i][e] = 0.0f;

        #pragma unroll
        for (int ks = 0; ks < 64; ks += 16) {
            unsigned a[4], b0[4], b1[4];
            ldm4(a,  qBase + aoff + ks * 2);
            ldm4(b0, kb + boff[0] + ks * 2);
            ldm4(b1, kb + boff[1] + ks * 2);
            mma16(c[0], a, &b0[0]);
            mma16(c[1], a, &b0[2]);
            mma16(c[2], a, &b1[0]);
            mma16(c[3], a, &b1[2]);
        }

        // mask + scale
        float vals[4][4];
        #pragma unroll
        for (int nt = 0; nt < 4; nt++) {
            const int col = nc * 128 + wn * 32 + nt * 8 + 2 * t;
            const int mA = mask[zb * SS + col];
            const int mB = mask[zb * SS + col + 1];
            vals[nt][0] = mA ? c[nt][0] * 0.125f : -1e9f;
            vals[nt][1] = mB ? c[nt][1] * 0.125f : -1e9f;
            vals[nt][2] = mA ? c[nt][2] * 0.125f : -1e9f;
            vals[nt][3] = mB ? c[nt][3] * 0.125f : -1e9f;
        }

        if (it < 8) {
            // ---- pass 1: online max/sum (rows g and g+8) ----
            float m0c = -1e30f, m1c = -1e30f;
            #pragma unroll
            for (int nt = 0; nt < 4; nt++) {
                m0c = fmaxf(m0c, fmaxf(vals[nt][0], vals[nt][1]));
                m1c = fmaxf(m1c, fmaxf(vals[nt][2], vals[nt][3]));
            }
            #pragma unroll
            for (int o = 1; o <= 2; o <<= 1) {
                m0c = fmaxf(m0c, __shfl_xor_sync(0xffffffffu, m0c, o));
                m1c = fmaxf(m1c, __shfl_xor_sync(0xffffffffu, m1c, o));
            }
            const float n0 = fmaxf(mrun0, m0c), n1 = fmaxf(mrun1, m1c);
            float s0 = 0.0f, s1 = 0.0f;
            #pragma unroll
            for (int nt = 0; nt < 4; nt++) {
                s0 += __expf(vals[nt][0] - n0) + __expf(vals[nt][1] - n0);
                s1 += __expf(vals[nt][2] - n1) + __expf(vals[nt][3] - n1);
            }
            #pragma unroll
            for (int o = 1; o <= 2; o <<= 1) {
                s0 += __shfl_xor_sync(0xffffffffu, s0, o);
                s1 += __shfl_xor_sync(0xffffffffu, s1, o);
            }
            srun0 = srun0 * __expf(mrun0 - n0) + s0; mrun0 = n0;
            srun1 = srun1 * __expf(mrun1 - n1) + s1; mrun1 = n1;
        } else {
            // ---- pass 2: write final attn ----
            const int r0 = wm * 16 + g, r1 = r0 + 8;
            const float fm0 = fM[r0], fi0 = fI[r0];
            const float fm1 = fM[r1], fi1 = fI[r1];
            const long b0r = zbase + (long)(m0r + r0) * SS;
            const long b1r = zbase + (long)(m0r + r1) * SS;
            #pragma unroll
            for (int nt = 0; nt < 4; nt++) {
                const int col = nc * 128 + wn * 32 + nt * 8 + 2 * t;
                float w00 = __expf(vals[nt][0] - fm0) * fi0;
                float w01 = __expf(vals[nt][1] - fm0) * fi0;
                float w10 = __expf(vals[nt][2] - fm1) * fi1;
                float w11 = __expf(vals[nt][3] - fm1) * fi1;
                *(float2*)&outa[b0r + col] = make_float2(w00, w01);
                *(float2*)&outa[b1r + col] = make_float2(w10, w11);
                *(__half2*)(ah + b0r + col) = __floats2half2_rn(w00, w01);
                *(__half2*)(ah + b1r + col) = __floats2half2_rn(w10, w11);
            }
        }
    }
}

// ---------------- float -> half convert (vectorized) -------------------------
__global__ void __launch_bounds__(256)
cvt_k(const float* __restrict__ in, __half* __restrict__ out, int n4)
{
    int i = blockIdx.x * 256 + threadIdx.x;
    if (i < n4) {
        float4 v = ((const float4*)in)[i];
        ((__half2*)out)[2*i]   = __floats2half2_rn(v.x, v.y);
        ((__half2*)out)[2*i+1] = __floats2half2_rn(v.z, v.w);
    }
}

// ---------------- V transpose: kv[token][1024+h*64+dk] -> vt[b,h][dk][s] -----
__global__ void __launch_bounds__(256)
vt_k(const __half* __restrict__ v, int ldv, __half* __restrict__ vt)
{
    __shared__ __half tile[64][72];
    const int z = blockIdx.z;
    const int b = z >> 4, h = z & 15;
    const int s0 = blockIdx.x * 64;
    const int tid = threadIdx.x;

    #pragma unroll
    for (int p = 0; p < 2; p++) {
        int r   = p * 32 + (tid >> 3);
        int seg = tid & 7;
        uint4 d = *(const uint4*)(v + ((long)(b * SS + s0 + r)) * ldv + h * 64 + seg * 8);
        *(uint4*)&tile[r][seg * 8] = d;
    }
    __syncthreads();
    #pragma unroll
    for (int p = 0; p < 2; p++) {
        int c   = p * 32 + (tid >> 3);
        int seg = tid & 7;
        __half tmp[8];
        #pragma unroll
        for (int j = 0; j < 8; j++) tmp[j] = tile[seg * 8 + j][c];
        *(uint4*)(vt + ((long)z * 64 + c) * SS + s0 + seg * 8) = *(uint4*)tmp;
    }
}

// ---------------- LayerNorm over D=1024; half output -------------------------
__global__ void __launch_bounds__(256)
ln_k(const float* __restrict__ x, const float* __restrict__ g,
     const float* __restrict__ b, __half* __restrict__ o)
{
    __shared__ float red[8];
    const long row = blockIdx.x;
    const int  t = threadIdx.x, lane = t & 31, w = t >> 5;

    float4 v = ((const float4*)(x + row * DD))[t];
    float s = v.x + v.y + v.z + v.w;
    #pragma unroll
    for (int off = 16; off; off >>= 1) s += __shfl_down_sync(0xffffffffu, s, off);
    if (!lane) red[w] = s;
    __syncthreads();
    if (t == 0) { float a = 0.f; for (int i = 0; i < 8; i++) a += red[i]; red[0] = a; }
    __syncthreads();
    const float mu = red[0] * (1.0f / DD);
    __syncthreads();

    float d0 = v.x - mu, d1 = v.y - mu, d2 = v.z - mu, d3 = v.w - mu;
    float sq = d0*d0 + d1*d1 + d2*d2 + d3*d3;
    #pragma unroll
    for (int off = 16; off; off >>= 1) sq += __shfl_down_sync(0xffffffffu, sq, off);
    if (!lane) red[w] = sq;
    __syncthreads();
    if (t == 0) { float a = 0.f; for (int i = 0; i < 8; i++) a += red[i]; red[0] = a; }
    __syncthreads();
    const float rs = rsqrtf(red[0] * (1.0f / DD) + 1e-5f);

    float4 g4 = ((const float4*)g)[t];
    float4 b4 = ((const float4*)b)[t];
    __half2* op = (__half2*)(o + row * DD);
    op[2*t]   = __floats2half2_rn(d0 * rs * g4.x + b4.x, d1 * rs * g4.y + b4.y);
    op[2*t+1] = __floats2half2_rn(d2 * rs * g4.z + b4.z, d3 * rs * g4.w + b4.w);
}

// ---------------- host orchestration ----------------------------------------
extern "C" void kernel_launch(void* const* d_in, const int* in_sizes, int n_in,
                              void* d_out, int out_size)
{
    const float* x    = (const float*)d_in[0];
    const int*   mask = (const int*)  d_in[1];
    const float* Wq = (const float*)d_in[2];  const float* bq = (const float*)d_in[3];
    const float* Wk = (const float*)d_in[4];  const float* bk = (const float*)d_in[5];
    const float* Wv = (const float*)d_in[6];  const float* bv = (const float*)d_in[7];
    const float* Wo = (const float*)d_in[8];  const float* bo = (const float*)d_in[9];
    const float* lag = (const float*)d_in[10]; const float* lab = (const float*)d_in[11];
    const float* W1 = (const float*)d_in[12]; const float* b1 = (const float*)d_in[13];
    const float* W2 = (const float*)d_in[14]; const float* b2 = (const float*)d_in[15];
    const float* lfg = (const float*)d_in[16]; const float* lfb = (const float*)d_in[17];
    const float* bnffg = (const float*)d_in[18]; const float* bnffb = (const float*)d_in[19];
    const float* bnffm = (const float*)d_in[20]; const float* bnffv = (const float*)d_in[21];
    const float* bn1g = (const float*)d_in[22]; const float* bn1b = (const float*)d_in[23];
    const float* bn1m = (const float*)d_in[24]; const float* bn1v = (const float*)d_in[25];
    const float* bn2g = (const float*)d_in[26]; const float* bn2b = (const float*)d_in[27];
    const float* bn2m = (const float*)d_in[28]; const float* bn2v = (const float*)d_in[29];

    __half *xq, *xr, *q, *kv, *vt, *ctx, *h, *w, *ah;
    float *x1;
    cudaGetSymbolAddress((void**)&xq,  g_xq);
    cudaGetSymbolAddress((void**)&xr,  g_xr);
    cudaGetSymbolAddress((void**)&q,   g_q);
    cudaGetSymbolAddress((void**)&kv,  g_kv);
    cudaGetSymbolAddress((void**)&vt,  g_vt);
    cudaGetSymbolAddress((void**)&ctx, g_ctx);
    cudaGetSymbolAddress((void**)&x1,  g_x1);
    cudaGetSymbolAddress((void**)&h,   g_h);
    cudaGetSymbolAddress((void**)&w,   g_w);
    cudaGetSymbolAddress((void**)&ah,  g_ah);

    __half* cWq = w;
    __half* cWk = w + 1*1024*1024;     // cWk..cWv contiguous = fused KV weight
    __half* cWv = w + 2*1024*1024;
    __half* cWo = w + 3*1024*1024;
    __half* cW1 = w + 4*1024*1024;
    __half* cW2 = w + 8*1024*1024;

    float* outx = (float*)d_out;                    // [B,S,D]
    float* outa = outx + (long)NTOK * DD;           // [B,H,S,S]

    constexpr int SM_B   = 4 * (128*80 + 256*80);       // 122880 B (big NT GEMMs)
    constexpr int SM_AV  = 3 * (128*80 +  64*80);       // 46080 B (attn@V)
    constexpr int SM_SF2 = 32*144 + 3*128*144 + 1280;   // 61184 B (two-pass softmax)

    //                 BM  BN  WM WN ST  MODE OUTH
    auto* kP  = gemm_h<128,256,64,64,4,  0,   true >;  // q / kv -> half
    auto* kAV = gemm_h<128, 64,32,32,3,  4,   true >;  // attn_h @ Vt -> ctx half
    auto* kR  = gemm_h<128,256,64,64,4,  1,   false>;  // O-proj / W2 -> fp32
    auto* kG  = gemm_h<128,256,64,64,4,  2,   true >;  // W1 -> h half
    cudaFuncSetAttribute((const void*)kP,  cudaFuncAttributeMaxDynamicSharedMemorySize, SM_B);
    cudaFuncSetAttribute((const void*)kAV, cudaFuncAttributeMaxDynamicSharedMemorySize, SM_AV);
    cudaFuncSetAttribute((const void*)kR,  cudaFuncAttributeMaxDynamicSharedMemorySize, SM_B);
    cudaFuncSetAttribute((const void*)kG,  cudaFuncAttributeMaxDynamicSharedMemorySize, SM_B);
    cudaFuncSetAttribute((const void*)sf2_k, cudaFuncAttributeMaxDynamicSharedMemorySize, SM_SF2);

    // 0) convert weights + x to half
    cvt_k<<<(1024*1024/4 + 255)/256, 256>>>(Wq, cWq, 1024*1024/4);
    cvt_k<<<(1024*1024/4 + 255)/256, 256>>>(Wk, cWk, 1024*1024/4);
    cvt_k<<<(1024*1024/4 + 255)/256, 256>>>(Wv, cWv, 1024*1024/4);
    cvt_k<<<(1024*1024/4 + 255)/256, 256>>>(Wo, cWo, 1024*1024/4);
    cvt_k<<<(4*1024*1024/4 + 255)/256, 256>>>(W1, cW1, 4*1024*1024/4);
    cvt_k<<<(4*1024*1024/4 + 255)/256, 256>>>(W2, cW2, 4*1024*1024/4);
    cvt_k<<<(NTOK*DD/4 + 255)/256, 256>>>(x, xr, NTOK*DD/4);

    // 1) pre-LN for query path (half out)
    ln_k<<<NTOK, 256>>>(x, lag, lab, xq);

    // 2) q projection (N=1024) + fused kv projection (N=2048)
    dim3 gQ(DD / 256, NTOK / 128, 1);
    kP<<<gQ, 256, SM_B>>>(xq, DD,0,0, cWq, DD,0,0, q, DD,0,0, DD,
        bq, nullptr, nullptr,0, nullptr,nullptr,nullptr,nullptr);
    dim3 gKV(2048 / 256, NTOK / 128, 1);
    kP<<<gKV, 256, SM_B>>>(xr, DD,0,0, cWk, DD,0,0, kv, 2048,0,0, DD,
        bk, bv, nullptr,0, nullptr,nullptr,nullptr,nullptr);

    // 2b) transpose V part of kv: [s, dk] -> [dk, s] per (b,h)
    dim3 gV(SS / 64, 1, BB * HH);
    vt_k<<<gV, 256>>>(kv + 1024, 2048, vt);

    // 3+4) fused scores + mask + softmax (two-pass, no scores buffer)
    dim3 gSF(SS / 32, 1, BB * HH);
    sf2_k<<<gSF, 256, SM_SF2>>>(q, kv, outa, ah, mask);

    // 5) context = attn_h @ Vt  (all-half NT GEMM)
    dim3 gC(1, SS / 128, BB * HH);
    kAV<<<gC, 256, SM_AV>>>(
        ah,   SS, (long)HH * SS * SS, (long)SS * SS,
        vt,   SS, (long)HH * DKK * SS, (long)DKK * SS,
        ctx,  DD, (long)SS * DD, 64,
        SS, nullptr, nullptr, nullptr,0, nullptr,nullptr,nullptr,nullptr);

    // 6) O projection + residual(x) + bn1 -> x1 (fp32)
    dim3 gO(DD / 256, NTOK / 128, 1);
    kR<<<gO, 256, SM_B>>>(ctx, DD,0,0, cWo, DD,0,0, x1, DD,0,0, DD,
        bo, nullptr, x, DD, bn1g,bn1b,bn1m,bn1v);

    // 7) FFN pre-LN (half out)
    ln_k<<<NTOK, 256>>>(x1, lfg, lfb, xq);

    // 8) h = bnff(gelu(xn W1^T + b1)) -> half  M=8192 N=4096 K=1024
    dim3 g1(DF / 256, NTOK / 128, 1);
    kG<<<g1, 256, SM_B>>>(xq, DD,0,0, cW1, DD,0,0, h, DF,0,0, DD,
        b1, nullptr, nullptr,0, bnffg,bnffb,bnffm,bnffv);

    // 9) out_x = bn2(h W2^T + b2 + x1)  M=8192 N=1024 K=4096
    dim3 g2(DD / 256, NTOK / 128, 1);
    kR<<<g2, 256, SM_B>>>(h, DF,0,0, cW2, DF,0,0, outx, DD,0,0, DF,
        b2, nullptr, x1, DD, bn2g,bn2b,bn2m,bn2v);
}

// round 13
// speedup vs baseline: 1.0417x; 1.0175x over previous
#include <cuda_runtime.h>
#include <cuda_fp16.h>
#include <math.h>
#include <stdint.h>

#define BB   8
#define SS   1024
#define DD   1024
#define HH   16
#define DKK  64
#define DF   4096
#define NTOK (BB*SS)        // 8192 tokens

// ---------------- scratch (static device globals; no allocation) ------------
__device__ __half g_xq[NTOK*DD];       // LN output (half), both LNs
__device__ __half g_xr[NTOK*DD];       // x as half
__device__ __half g_q [NTOK*DD];
__device__ __half g_kv[NTOK*2048];     // fused K|V: [token][0:1024)=k, [1024:2048)=v
__device__ __half g_vt[NTOK*DD];       // [b,h][dk][token] transposed V
__device__ __half g_ctx[NTOK*DD];
__device__ float  g_x1[NTOK*DD];       // after bn1 (exact fp32)
__device__ __half g_h [NTOK*DF];       // FFN hidden
__device__ __half g_w [12*1024*1024];  // half weights: Wq Wk Wv Wo | W1 | W2
__device__ __half g_ah[134217728];     // attn as half (B*H*S*S) for AV GEMM

// ---------------- helpers ----------------------------------------------------
__device__ __forceinline__ void cpa16(void* s, const void* g) {
    unsigned sa = (unsigned)__cvta_generic_to_shared(s);
    asm volatile("cp.async.cg.shared.global [%0], [%1], 16;" :: "r"(sa), "l"(g));
}
__device__ __forceinline__ void cpa16u(uint32_t sa, const void* g) {
    asm volatile("cp.async.cg.shared.global [%0], [%1], 16;" :: "r"(sa), "l"(g));
}
__device__ __forceinline__ void cp_commit() { asm volatile("cp.async.commit_group;"); }
template<int N> __device__ __forceinline__ void cp_wait() {
    asm volatile("cp.async.wait_group %0;" :: "n"(N));
}
__device__ __forceinline__ void mma16(float* c, const unsigned* a, const unsigned* b) {
    asm volatile(
        "mma.sync.aligned.m16n8k16.row.col.f32.f16.f16.f32 "
        "{%0,%1,%2,%3}, {%4,%5,%6,%7}, {%8,%9}, {%0,%1,%2,%3};"
        : "+f"(c[0]), "+f"(c[1]), "+f"(c[2]), "+f"(c[3])
        : "r"(a[0]), "r"(a[1]), "r"(a[2]), "r"(a[3]), "r"(b[0]), "r"(b[1]));
}
__device__ __forceinline__ void ldm4(unsigned* r, uint32_t addr) {
    asm volatile("ldmatrix.sync.aligned.m8n8.x4.shared.b16 {%0,%1,%2,%3}, [%4];"
                 : "=r"(r[0]), "=r"(r[1]), "=r"(r[2]), "=r"(r[3]) : "r"(addr));
}

// ---------------- fp16 tensor-core GEMM (ST-stage cp.async + ldmatrix, NT) ---
// C[M,N] = A[M,K] * B[N,K]^T + epilogue. A,B half, K-major.
// bias2: if non-null, cols >=1024 use bias2[n-1024] (fused KV projection).
// MODE: 0 bias | 1 bias+res+BN | 2 bias+GELU+BN | 4 raw
template<int BM,int BN,int WM,int WN,int ST,int MODE,bool OUTH>
__global__ void __launch_bounds__(256)
gemm_h(const __half* __restrict__ A, int lda, long aS1, long aS2,
       const __half* __restrict__ B, int ldb, long bS1, long bS2,
       void* __restrict__ Cv, int ldc, long cS1, long cS2,
       int K,
       const float* __restrict__ bias, const float* __restrict__ bias2,
       const float* __restrict__ res, int ldres,
       const float* __restrict__ bng, const float* __restrict__ bnb,
       const float* __restrict__ bnm, const float* __restrict__ bnv)
{
    constexpr int BK  = 32;
    constexpr int ASZ = BM * 80;
    constexpr int BSZ = BN * 80;

    extern __shared__ char smem[];
    const uint32_t smem_u = (uint32_t)__cvta_generic_to_shared(smem);

    const int z  = blockIdx.z;
    const int zb = z >> 4;
    const int zh = z & 15;
    A += (long)zb * aS1 + (long)zh * aS2;
    B += (long)zb * bS1 + (long)zh * bS2;

    const int tid = threadIdx.x;
    const int m0  = blockIdx.y * BM;
    const int n0  = blockIdx.x * BN;

    const int warp = tid >> 5, lane = tid & 31;
    constexpr int WGN = BN / WN;
    const int wm = warp / WGN, wn = warp % WGN;
    const int g  = lane >> 2,  t  = lane & 3;
    constexpr int MT  = WM / 16;
    constexpr int NTL = WN / 8;

    const int arow  = (lane & 7) | (((lane >> 3) & 1) << 3);
    const int akofs = (lane >> 4) << 3;
    const int brow  = ((lane >> 4) << 3) | (lane & 7);
    const int bkofs = ((lane >> 3) & 1) << 3;
    uint32_t aoff[MT], boff[NTL/2];
    #pragma unroll
    for (int mt = 0; mt < MT; mt++)
        aoff[mt] = ((wm * WM + mt * 16 + arow) * 40 + akofs) * 2;
    #pragma unroll
    for (int p = 0; p < NTL/2; p++)
        boff[p] = ((wn * WN + p * 16 + brow) * 40 + bkofs) * 2;

    float c[MT][NTL][4];
    #pragma unroll
    for (int i = 0; i < MT; i++)
        #pragma unroll
        for (int j = 0; j < NTL; j++)
            #pragma unroll
            for (int e = 0; e < 4; e++) c[i][j][e] = 0.0f;

    const int iters = K / BK;

    auto load_stage = [&](int it, int buf) {
        const int k0 = it * BK;
        char* dA = smem + buf * ASZ;
        char* dB = smem + ST * ASZ + buf * BSZ;
        #pragma unroll
        for (int s = tid; s < BM * 4; s += 256) {
            int row = s >> 2, seg = s & 3;
            cpa16(dA + row * 80 + seg * 16,
                  A + (long)(m0 + row) * lda + k0 + seg * 8);
        }
        #pragma unroll
        for (int s = tid; s < BN * 4; s += 256) {
            int row = s >> 2, seg = s & 3;
            cpa16(dB + row * 80 + seg * 16,
                  B + (long)(n0 + row) * ldb + k0 + seg * 8);
        }
    };

    #pragma unroll
    for (int s = 0; s < ST - 1; s++) {
        if (s < iters) load_stage(s, s);
        cp_commit();
    }

    for (int it = 0; it < iters; ++it) {
        cp_wait<ST - 2>();
        __syncthreads();

        if (it + ST - 1 < iters) load_stage(it + ST - 1, (it + ST - 1) % ST);
        cp_commit();

        const int buf = it % ST;
        const uint32_t aBase = smem_u + buf * ASZ;
        const uint32_t bBase = smem_u + ST * ASZ + buf * BSZ;

        #pragma unroll
        for (int ks = 0; ks < BK; ks += 16) {
            unsigned a[MT][4], b[NTL/2][4];
            #pragma unroll
            for (int mt = 0; mt < MT; mt++)
                ldm4(a[mt], aBase + aoff[mt] + ks * 2);
            #pragma unroll
            for (int p = 0; p < NTL/2; p++)
                ldm4(b[p], bBase + boff[p] + ks * 2);
            #pragma unroll
            for (int mt = 0; mt < MT; mt++)
                #pragma unroll
                for (int p = 0; p < NTL/2; p++) {
                    mma16(c[mt][2*p],   a[mt], &b[p][0]);
                    mma16(c[mt][2*p+1], a[mt], &b[p][2]);
                }
        }
    }

    auto ep = [&](float v, int n, long m) -> float {
        if constexpr (MODE == 0) {
            v += (bias2 && n >= 1024) ? bias2[n - 1024] : bias[n];
        } else if constexpr (MODE == 1) {
            v += bias[n] + res[m * ldres + n];
            v = (v - bnm[n]) * rsqrtf(bnv[n] + 1e-5f) * bng[n] + bnb[n];
        } else if constexpr (MODE == 2) {
            v += bias[n];
            v = 0.5f * v * (1.0f + erff(v * 0.70710678118654752f));
            v = (v - bnm[n]) * rsqrtf(bnv[n] + 1e-5f) * bng[n] + bnb[n];
        }
        return v;
    };

    const long cofs = (long)zb * cS1 + (long)zh * cS2;
    #pragma unroll
    for (int mt = 0; mt < MT; mt++) {
        #pragma unroll
        for (int nt = 0; nt < NTL; nt++) {
            const int row = m0 + wm * WM + mt * 16 + g;
            const int col = n0 + wn * WN + nt * 8 + 2 * t;
            float v00 = ep(c[mt][nt][0], col,     row);
            float v01 = ep(c[mt][nt][1], col + 1, row);
            float v10 = ep(c[mt][nt][2], col,     row + 8);
            float v11 = ep(c[mt][nt][3], col + 1, row + 8);
            if constexpr (OUTH) {
                __half* Ch = (__half*)Cv + cofs;
                *(__half2*)(Ch + (long)(row    ) * ldc + col) = __floats2half2_rn(v00, v01);
                *(__half2*)(Ch + (long)(row + 8) * ldc + col) = __floats2half2_rn(v10, v11);
            } else {
                float* Cf = (float*)Cv + cofs;
                *(float2*)(Cf + (long)(row    ) * ldc + col) = make_float2(v00, v01);
                *(float2*)(Cf + (long)(row + 8) * ldc + col) = make_float2(v10, v11);
            }
        }
    }
}

// ---------------- fused scores+mask+softmax, two-pass online, ROWS=64 --------
// Block: 64 query rows x one (b,h). 8 warps = 4 row-groups x 2 col-halves.
// Pass 1 (it 0-7): online row max/sum. Cross-warp reduction at it==8.
// Pass 2 (it 8-15): recompute scores, write final attn fp32 (d_out) + half (ah).
__global__ void __launch_bounds__(256)
sf2_k(const __half* __restrict__ q,
      const __half* __restrict__ kv,
      float* __restrict__ outa,
      __half* __restrict__ ah,
      const int* __restrict__ mask)
{
    constexpr int ROWS = 64;
    constexpr int QSZ  = ROWS * 144;       // 9216
    constexpr int KSZ  = 128 * 144;        // 18432

    extern __shared__ char smem[];
    const uint32_t smem_u = (uint32_t)__cvta_generic_to_shared(smem);
    const uint32_t qBase = smem_u;
    const uint32_t kBase = smem_u + QSZ;
    float* sM  = (float*)(smem + QSZ + 3 * KSZ);   // [64][2]
    float* sSm = sM + 128;                          // [64][2]
    float* fM  = sSm + 128;                         // [64]
    float* fI  = fM + 64;                           // [64]

    const int z  = blockIdx.z;
    const int zb = z >> 4;
    const int zh = z & 15;
    const int m0r = blockIdx.x * ROWS;

    const int tid = threadIdx.x;
    const int warp = tid >> 5, lane = tid & 31;
    const int wm = warp >> 1, wn = warp & 1;        // 4 x 2 warps: WM=16, WN=64
    const int g  = lane >> 2,  t = lane & 3;

    const int arow  = (lane & 7) | (((lane >> 3) & 1) << 3);
    const int akofs = (lane >> 4) << 3;
    const int brow  = ((lane >> 4) << 3) | (lane & 7);
    const int bkofs = ((lane >> 3) & 1) << 3;
    const uint32_t aoff = ((wm * 16 + arow) * 72 + akofs) * 2;
    uint32_t boff[4];
    #pragma unroll
    for (int p = 0; p < 4; p++)
        boff[p] = ((wn * 64 + p * 16 + brow) * 72 + bkofs) * 2;

    auto load_q = [&] {
        #pragma unroll
        for (int s = tid; s < ROWS * 8; s += 256) {
            int row = s >> 3, seg = s & 7;
            cpa16u(qBase + row * 144 + seg * 16,
                   q + (long)(zb * SS + m0r + row) * DD + zh * 64 + seg * 8);
        }
    };
    auto load_k = [&](int nc, int buf) {
        #pragma unroll
        for (int s = tid; s < 1024; s += 256) {
            int row = s >> 3, seg = s & 7;
            cpa16u(kBase + buf * KSZ + row * 144 + seg * 16,
                   kv + (long)(zb * SS + nc * 128 + row) * 2048 + zh * 64 + seg * 8);
        }
    };

    load_q(); load_k(0, 0); cp_commit();
    load_k(1, 1); cp_commit();

    float mrun0 = -1e30f, mrun1 = -1e30f, srun0 = 0.0f, srun1 = 0.0f;
    const long zbase = (long)z * SS * SS;

    for (int it = 0; it < 16; ++it) {
        const int nc = it & 7;
        cp_wait<1>();
        __syncthreads();
        if (it + 2 < 16) load_k((it + 2) & 7, (it + 2) % 3);
        cp_commit();

        // ---- cross-warp softmax stats reduction between passes ----
        if (it == 8) {
            if (t == 0) {
                const int r0 = wm * 16 + g;
                sM [r0 * 2 + wn] = mrun0;  sSm[r0 * 2 + wn] = srun0;
                sM [(r0+8) * 2 + wn] = mrun1;  sSm[(r0+8) * 2 + wn] = srun1;
            }
            __syncthreads();
            if (tid < 64) {
                float m = fmaxf(sM[tid*2], sM[tid*2+1]);
                float s = sSm[tid*2]   * __expf(sM[tid*2]   - m)
                        + sSm[tid*2+1] * __expf(sM[tid*2+1] - m);
                fM[tid] = m; fI[tid] = 1.0f / s;
            }
            __syncthreads();
        }

        const uint32_t kb = kBase + (it % 3) * KSZ;
        float c[8][4];
        #pragma unroll
        for (int i = 0; i < 8; i++)
            #pragma unroll
            for (int e = 0; e < 4; e++) c[i][e] = 0.0f;

        #pragma unroll
        for (int ks = 0; ks < 64; ks += 16) {
            unsigned a[4], b[4][4];
            ldm4(a, qBase + aoff + ks * 2);
            #pragma unroll
            for (int p = 0; p < 4; p++)
                ldm4(b[p], kb + boff[p] + ks * 2);
            #pragma unroll
            for (int p = 0; p < 4; p++) {
                mma16(c[2*p],   a, &b[p][0]);
                mma16(c[2*p+1], a, &b[p][2]);
            }
        }

        // mask + scale
        float vals[8][4];
        #pragma unroll
        for (int j = 0; j < 8; j++) {
            const int col = nc * 128 + wn * 64 + j * 8 + 2 * t;
            const int mA = mask[zb * SS + col];
            const int mB = mask[zb * SS + col + 1];
            vals[j][0] = mA ? c[j][0] * 0.125f : -1e9f;
            vals[j][1] = mB ? c[j][1] * 0.125f : -1e9f;
            vals[j][2] = mA ? c[j][2] * 0.125f : -1e9f;
            vals[j][3] = mB ? c[j][3] * 0.125f : -1e9f;
        }

        if (it < 8) {
            // ---- pass 1: online max/sum (rows g and g+8) ----
            float m0c = -1e30f, m1c = -1e30f;
            #pragma unroll
            for (int j = 0; j < 8; j++) {
                m0c = fmaxf(m0c, fmaxf(vals[j][0], vals[j][1]));
                m1c = fmaxf(m1c, fmaxf(vals[j][2], vals[j][3]));
            }
            #pragma unroll
            for (int o = 1; o <= 2; o <<= 1) {
                m0c = fmaxf(m0c, __shfl_xor_sync(0xffffffffu, m0c, o));
                m1c = fmaxf(m1c, __shfl_xor_sync(0xffffffffu, m1c, o));
            }
            const float n0 = fmaxf(mrun0, m0c), n1 = fmaxf(mrun1, m1c);
            float s0 = 0.0f, s1 = 0.0f;
            #pragma unroll
            for (int j = 0; j < 8; j++) {
                s0 += __expf(vals[j][0] - n0) + __expf(vals[j][1] - n0);
                s1 += __expf(vals[j][2] - n1) + __expf(vals[j][3] - n1);
            }
            #pragma unroll
            for (int o = 1; o <= 2; o <<= 1) {
                s0 += __shfl_xor_sync(0xffffffffu, s0, o);
                s1 += __shfl_xor_sync(0xffffffffu, s1, o);
            }
            srun0 = srun0 * __expf(mrun0 - n0) + s0; mrun0 = n0;
            srun1 = srun1 * __expf(mrun1 - n1) + s1; mrun1 = n1;
        } else {
            // ---- pass 2: write final attn ----
            const int r0 = wm * 16 + g, r1 = r0 + 8;
            const float fm0 = fM[r0], fi0 = fI[r0];
            const float fm1 = fM[r1], fi1 = fI[r1];
            const long b0r = zbase + (long)(m0r + r0) * SS;
            const long b1r = zbase + (long)(m0r + r1) * SS;
            #pragma unroll
            for (int j = 0; j < 8; j++) {
                const int col = nc * 128 + wn * 64 + j * 8 + 2 * t;
                float w00 = __expf(vals[j][0] - fm0) * fi0;
                float w01 = __expf(vals[j][1] - fm0) * fi0;
                float w10 = __expf(vals[j][2] - fm1) * fi1;
                float w11 = __expf(vals[j][3] - fm1) * fi1;
                *(float2*)&outa[b0r + col] = make_float2(w00, w01);
                *(float2*)&outa[b1r + col] = make_float2(w10, w11);
                *(__half2*)(ah + b0r + col) = __floats2half2_rn(w00, w01);
                *(__half2*)(ah + b1r + col) = __floats2half2_rn(w10, w11);
            }
        }
    }
}

// ---------------- float -> half convert (vectorized) -------------------------
__global__ void __launch_bounds__(256)
cvt_k(const float* __restrict__ in, __half* __restrict__ out, int n4)
{
    int i = blockIdx.x * 256 + threadIdx.x;
    if (i < n4) {
        float4 v = ((const float4*)in)[i];
        ((__half2*)out)[2*i]   = __floats2half2_rn(v.x, v.y);
        ((__half2*)out)[2*i+1] = __floats2half2_rn(v.z, v.w);
    }
}

// ---------------- V transpose: kv[token][1024+h*64+dk] -> vt[b,h][dk][s] -----
__global__ void __launch_bounds__(256)
vt_k(const __half* __restrict__ v, int ldv, __half* __restrict__ vt)
{
    __shared__ __half tile[64][72];
    const int z = blockIdx.z;
    const int b = z >> 4, h = z & 15;
    const int s0 = blockIdx.x * 64;
    const int tid = threadIdx.x;

    #pragma unroll
    for (int p = 0; p < 2; p++) {
        int r   = p * 32 + (tid >> 3);
        int seg = tid & 7;
        uint4 d = *(const uint4*)(v + ((long)(b * SS + s0 + r)) * ldv + h * 64 + seg * 8);
        *(uint4*)&tile[r][seg * 8] = d;
    }
    __syncthreads();
    #pragma unroll
    for (int p = 0; p < 2; p++) {
        int c   = p * 32 + (tid >> 3);
        int seg = tid & 7;
        __half tmp[8];
        #pragma unroll
        for (int j = 0; j < 8; j++) tmp[j] = tile[seg * 8 + j][c];
        *(uint4*)(vt + ((long)z * 64 + c) * SS + s0 + seg * 8) = *(uint4*)tmp;
    }
}

// ---------------- LayerNorm over D=1024; half output -------------------------
__global__ void __launch_bounds__(256)
ln_k(const float* __restrict__ x, const float* __restrict__ g,
     const float* __restrict__ b, __half* __restrict__ o)
{
    __shared__ float red[8];
    const long row = blockIdx.x;
    const int  t = threadIdx.x, lane = t & 31, w = t >> 5;

    float4 v = ((const float4*)(x + row * DD))[t];
    float s = v.x + v.y + v.z + v.w;
    #pragma unroll
    for (int off = 16; off; off >>= 1) s += __shfl_down_sync(0xffffffffu, s, off);
    if (!lane) red[w] = s;
    __syncthreads();
    if (t == 0) { float a = 0.f; for (int i = 0; i < 8; i++) a += red[i]; red[0] = a; }
    __syncthreads();
    const float mu = red[0] * (1.0f / DD);
    __syncthreads();

    float d0 = v.x - mu, d1 = v.y - mu, d2 = v.z - mu, d3 = v.w - mu;
    float sq = d0*d0 + d1*d1 + d2*d2 + d3*d3;
    #pragma unroll
    for (int off = 16; off; off >>= 1) sq += __shfl_down_sync(0xffffffffu, sq, off);
    if (!lane) red[w] = sq;
    __syncthreads();
    if (t == 0) { float a = 0.f; for (int i = 0; i < 8; i++) a += red[i]; red[0] = a; }
    __syncthreads();
    const float rs = rsqrtf(red[0] * (1.0f / DD) + 1e-5f);

    float4 g4 = ((const float4*)g)[t];
    float4 b4 = ((const float4*)b)[t];
    __half2* op = (__half2*)(o + row * DD);
    op[2*t]   = __floats2half2_rn(d0 * rs * g4.x + b4.x, d1 * rs * g4.y + b4.y);
    op[2*t+1] = __floats2half2_rn(d2 * rs * g4.z + b4.z, d3 * rs * g4.w + b4.w);
}

// ---------------- host orchestration ----------------------------------------
extern "C" void kernel_launch(void* const* d_in, const int* in_sizes, int n_in,
                              void* d_out, int out_size)
{
    const float* x    = (const float*)d_in[0];
    const int*   mask = (const int*)  d_in[1];
    const float* Wq = (const float*)d_in[2];  const float* bq = (const float*)d_in[3];
    const float* Wk = (const float*)d_in[4];  const float* bk = (const float*)d_in[5];
    const float* Wv = (const float*)d_in[6];  const float* bv = (const float*)d_in[7];
    const float* Wo = (const float*)d_in[8];  const float* bo = (const float*)d_in[9];
    const float* lag = (const float*)d_in[10]; const float* lab = (const float*)d_in[11];
    const float* W1 = (const float*)d_in[12]; const float* b1 = (const float*)d_in[13];
    const float* W2 = (const float*)d_in[14]; const float* b2 = (const float*)d_in[15];
    const float* lfg = (const float*)d_in[16]; const float* lfb = (const float*)d_in[17];
    const float* bnffg = (const float*)d_in[18]; const float* bnffb = (const float*)d_in[19];
    const float* bnffm = (const float*)d_in[20]; const float* bnffv = (const float*)d_in[21];
    const float* bn1g = (const float*)d_in[22]; const float* bn1b = (const float*)d_in[23];
    const float* bn1m = (const float*)d_in[24]; const float* bn1v = (const float*)d_in[25];
    const float* bn2g = (const float*)d_in[26]; const float* bn2b = (const float*)d_in[27];
    const float* bn2m = (const float*)d_in[28]; const float* bn2v = (const float*)d_in[29];

    __half *xq, *xr, *q, *kv, *vt, *ctx, *h, *w, *ah;
    float *x1;
    cudaGetSymbolAddress((void**)&xq,  g_xq);
    cudaGetSymbolAddress((void**)&xr,  g_xr);
    cudaGetSymbolAddress((void**)&q,   g_q);
    cudaGetSymbolAddress((void**)&kv,  g_kv);
    cudaGetSymbolAddress((void**)&vt,  g_vt);
    cudaGetSymbolAddress((void**)&ctx, g_ctx);
    cudaGetSymbolAddress((void**)&x1,  g_x1);
    cudaGetSymbolAddress((void**)&h,   g_h);
    cudaGetSymbolAddress((void**)&w,   g_w);
    cudaGetSymbolAddress((void**)&ah,  g_ah);

    __half* cWq = w;
    __half* cWk = w + 1*1024*1024;     // cWk..cWv contiguous = fused KV weight
    __half* cWv = w + 2*1024*1024;
    __half* cWo = w + 3*1024*1024;
    __half* cW1 = w + 4*1024*1024;
    __half* cW2 = w + 8*1024*1024;

    float* outx = (float*)d_out;                    // [B,S,D]
    float* outa = outx + (long)NTOK * DD;           // [B,H,S,S]

    constexpr int SM_B   = 4 * (128*80 + 256*80);       // 122880 B (big NT GEMMs)
    constexpr int SM_AV  = 3 * (128*80 +  64*80);       // 46080 B (attn@V)
    constexpr int SM_SF2 = 64*144 + 3*128*144 + 1536;   // 66048 B (two-pass softmax, ROWS=64)

    //                 BM  BN  WM WN ST  MODE OUTH
    auto* kP  = gemm_h<128,256,64,64,4,  0,   true >;  // q / kv -> half
    auto* kAV = gemm_h<128, 64,32,32,3,  4,   true >;  // attn_h @ Vt -> ctx half
    auto* kR  = gemm_h<128,256,64,64,4,  1,   false>;  // O-proj / W2 -> fp32
    auto* kG  = gemm_h<128,256,64,64,4,  2,   true >;  // W1 -> h half
    cudaFuncSetAttribute((const void*)kP,  cudaFuncAttributeMaxDynamicSharedMemorySize, SM_B);
    cudaFuncSetAttribute((const void*)kAV, cudaFuncAttributeMaxDynamicSharedMemorySize, SM_AV);
    cudaFuncSetAttribute((const void*)kR,  cudaFuncAttributeMaxDynamicSharedMemorySize, SM_B);
    cudaFuncSetAttribute((const void*)kG,  cudaFuncAttributeMaxDynamicSharedMemorySize, SM_B);
    cudaFuncSetAttribute((const void*)sf2_k, cudaFuncAttributeMaxDynamicSharedMemorySize, SM_SF2);

    // 0) convert weights + x to half
    cvt_k<<<(1024*1024/4 + 255)/256, 256>>>(Wq, cWq, 1024*1024/4);
    cvt_k<<<(1024*1024/4 + 255)/256, 256>>>(Wk, cWk, 1024*1024/4);
    cvt_k<<<(1024*1024/4 + 255)/256, 256>>>(Wv, cWv, 1024*1024/4);
    cvt_k<<<(1024*1024/4 + 255)/256, 256>>>(Wo, cWo, 1024*1024/4);
    cvt_k<<<(4*1024*1024/4 + 255)/256, 256>>>(W1, cW1, 4*1024*1024/4);
    cvt_k<<<(4*1024*1024/4 + 255)/256, 256>>>(W2, cW2, 4*1024*1024/4);
    cvt_k<<<(NTOK*DD/4 + 255)/256, 256>>>(x, xr, NTOK*DD/4);

    // 1) pre-LN for query path (half out)
    ln_k<<<NTOK, 256>>>(x, lag, lab, xq);

    // 2) q projection (N=1024) + fused kv projection (N=2048)
    dim3 gQ(DD / 256, NTOK / 128, 1);
    kP<<<gQ, 256, SM_B>>>(xq, DD,0,0, cWq, DD,0,0, q, DD,0,0, DD,
        bq, nullptr, nullptr,0, nullptr,nullptr,nullptr,nullptr);
    dim3 gKV(2048 / 256, NTOK / 128, 1);
    kP<<<gKV, 256, SM_B>>>(xr, DD,0,0, cWk, DD,0,0, kv, 2048,0,0, DD,
        bk, bv, nullptr,0, nullptr,nullptr,nullptr,nullptr);

    // 2b) transpose V part of kv: [s, dk] -> [dk, s] per (b,h)
    dim3 gV(SS / 64, 1, BB * HH);
    vt_k<<<gV, 256>>>(kv + 1024, 2048, vt);

    // 3+4) fused scores + mask + softmax (two-pass, ROWS=64)
    dim3 gSF(SS / 64, 1, BB * HH);
    sf2_k<<<gSF, 256, SM_SF2>>>(q, kv, outa, ah, mask);

    // 5) context = attn_h @ Vt  (all-half NT GEMM)
    dim3 gC(1, SS / 128, BB * HH);
    kAV<<<gC, 256, SM_AV>>>(
        ah,   SS, (long)HH * SS * SS, (long)SS * SS,
        vt,   SS, (long)HH * DKK * SS, (long)DKK * SS,
        ctx,  DD, (long)SS * DD, 64,
        SS, nullptr, nullptr, nullptr,0, nullptr,nullptr,nullptr,nullptr);

    // 6) O projection + residual(x) + bn1 -> x1 (fp32)
    dim3 gO(DD / 256, NTOK / 128, 1);
    kR<<<gO, 256, SM_B>>>(ctx, DD,0,0, cWo, DD,0,0, x1, DD,0,0, DD,
        bo, nullptr, x, DD, bn1g,bn1b,bn1m,bn1v);

    // 7) FFN pre-LN (half out)
    ln_k<<<NTOK, 256>>>(x1, lfg, lfb, xq);

    // 8) h = bnff(gelu(xn W1^T + b1)) -> half  M=8192 N=4096 K=1024
    dim3 g1(DF / 256, NTOK / 128, 1);
    kG<<<g1, 256, SM_B>>>(xq, DD,0,0, cW1, DD,0,0, h, DF,0,0, DD,
        b1, nullptr, nullptr,0, bnffg,bnffb,bnffm,bnffv);

    // 9) out_x = bn2(h W2^T + b2 + x1)  M=8192 N=1024 K=4096
    dim3 g2(DD / 256, NTOK / 128, 1);
    kR<<<g2, 256, SM_B>>>(h, DF,0,0, cW2, DF,0,0, outx, DD,0,0, DF,
        b2, nullptr, x1, DD, bn2g,bn2b,bn2m,bn2v);
}

// round 14
// speedup vs baseline: 1.1015x; 1.0574x over previous
#include <cuda_runtime.h>
#include <cuda_fp16.h>
#include <math.h>
#include <stdint.h>

#define BB   8
#define SS   1024
#define DD   1024
#define HH   16
#define DKK  64
#define DF   4096
#define NTOK (BB*SS)        // 8192 tokens

// ---------------- scratch (static device globals; no allocation) ------------
__device__ __half g_xq[NTOK*DD];       // LN output (half), both LNs
__device__ __half g_xr[NTOK*DD];       // x as half
__device__ __half g_q [NTOK*DD];
__device__ __half g_kv[NTOK*2048];     // fused K|V: [token][0:1024)=k, [1024:2048)=v
__device__ __half g_vt[NTOK*DD];       // [b,h][dk][token] transposed V
__device__ __half g_ctx[NTOK*DD];
__device__ float  g_x1[NTOK*DD];       // after bn1 (exact fp32)
__device__ __half g_h [NTOK*DF];       // FFN hidden
__device__ __half g_w [12*1024*1024];  // half weights: Wq Wk Wv Wo | W1 | W2

// ---------------- helpers ----------------------------------------------------
__device__ __forceinline__ void cpa16(void* s, const void* g) {
    unsigned sa = (unsigned)__cvta_generic_to_shared(s);
    asm volatile("cp.async.cg.shared.global [%0], [%1], 16;" :: "r"(sa), "l"(g));
}
__device__ __forceinline__ void cpa16u(uint32_t sa, const void* g) {
    asm volatile("cp.async.cg.shared.global [%0], [%1], 16;" :: "r"(sa), "l"(g));
}
__device__ __forceinline__ void cp_commit() { asm volatile("cp.async.commit_group;"); }
template<int N> __device__ __forceinline__ void cp_wait() {
    asm volatile("cp.async.wait_group %0;" :: "n"(N));
}
__device__ __forceinline__ void mma16(float* c, const unsigned* a, const unsigned* b) {
    asm volatile(
        "mma.sync.aligned.m16n8k16.row.col.f32.f16.f16.f32 "
        "{%0,%1,%2,%3}, {%4,%5,%6,%7}, {%8,%9}, {%0,%1,%2,%3};"
        : "+f"(c[0]), "+f"(c[1]), "+f"(c[2]), "+f"(c[3])
        : "r"(a[0]), "r"(a[1]), "r"(a[2]), "r"(a[3]), "r"(b[0]), "r"(b[1]));
}
__device__ __forceinline__ void ldm4(unsigned* r, uint32_t addr) {
    asm volatile("ldmatrix.sync.aligned.m8n8.x4.shared.b16 {%0,%1,%2,%3}, [%4];"
                 : "=r"(r[0]), "=r"(r[1]), "=r"(r[2]), "=r"(r[3]) : "r"(addr));
}
__device__ __forceinline__ unsigned packh2(float lo, float hi) {
    __half2 h = __floats2half2_rn(lo, hi);
    return *reinterpret_cast<unsigned*>(&h);
}

// ---------------- fp16 tensor-core GEMM (ST-stage cp.async + ldmatrix, NT) ---
// C[M,N] = A[M,K] * B[N,K]^T + epilogue. A,B half, K-major.
// bias2: if non-null, cols >=1024 use bias2[n-1024] (fused KV projection).
// MODE: 0 bias | 1 bias+res+BN | 2 bias+GELU+BN
template<int BM,int BN,int WM,int WN,int ST,int MODE,bool OUTH>
__global__ void __launch_bounds__(256)
gemm_h(const __half* __restrict__ A, int lda,
       const __half* __restrict__ B, int ldb,
       void* __restrict__ Cv, int ldc,
       int K,
       const float* __restrict__ bias, const float* __restrict__ bias2,
       const float* __restrict__ res, int ldres,
       const float* __restrict__ bng, const float* __restrict__ bnb,
       const float* __restrict__ bnm, const float* __restrict__ bnv)
{
    constexpr int BK  = 32;
    constexpr int ASZ = BM * 80;
    constexpr int BSZ = BN * 80;

    extern __shared__ char smem[];
    const uint32_t smem_u = (uint32_t)__cvta_generic_to_shared(smem);

    const int tid = threadIdx.x;
    const int m0  = blockIdx.y * BM;
    const int n0  = blockIdx.x * BN;

    const int warp = tid >> 5, lane = tid & 31;
    constexpr int WGN = BN / WN;
    const int wm = warp / WGN, wn = warp % WGN;
    const int g  = lane >> 2,  t  = lane & 3;
    constexpr int MT  = WM / 16;
    constexpr int NTL = WN / 8;

    const int arow  = (lane & 7) | (((lane >> 3) & 1) << 3);
    const int akofs = (lane >> 4) << 3;
    const int brow  = ((lane >> 4) << 3) | (lane & 7);
    const int bkofs = ((lane >> 3) & 1) << 3;
    uint32_t aoff[MT], boff[NTL/2];
    #pragma unroll
    for (int mt = 0; mt < MT; mt++)
        aoff[mt] = ((wm * WM + mt * 16 + arow) * 40 + akofs) * 2;
    #pragma unroll
    for (int p = 0; p < NTL/2; p++)
        boff[p] = ((wn * WN + p * 16 + brow) * 40 + bkofs) * 2;

    float c[MT][NTL][4];
    #pragma unroll
    for (int i = 0; i < MT; i++)
        #pragma unroll
        for (int j = 0; j < NTL; j++)
            #pragma unroll
            for (int e = 0; e < 4; e++) c[i][j][e] = 0.0f;

    const int iters = K / BK;

    auto load_stage = [&](int it, int buf) {
        const int k0 = it * BK;
        char* dA = smem + buf * ASZ;
        char* dB = smem + ST * ASZ + buf * BSZ;
        #pragma unroll
        for (int s = tid; s < BM * 4; s += 256) {
            int row = s >> 2, seg = s & 3;
            cpa16(dA + row * 80 + seg * 16,
                  A + (long)(m0 + row) * lda + k0 + seg * 8);
        }
        #pragma unroll
        for (int s = tid; s < BN * 4; s += 256) {
            int row = s >> 2, seg = s & 3;
            cpa16(dB + row * 80 + seg * 16,
                  B + (long)(n0 + row) * ldb + k0 + seg * 8);
        }
    };

    #pragma unroll
    for (int s = 0; s < ST - 1; s++) {
        if (s < iters) load_stage(s, s);
        cp_commit();
    }

    for (int it = 0; it < iters; ++it) {
        cp_wait<ST - 2>();
        __syncthreads();

        if (it + ST - 1 < iters) load_stage(it + ST - 1, (it + ST - 1) % ST);
        cp_commit();

        const int buf = it % ST;
        const uint32_t aBase = smem_u + buf * ASZ;
        const uint32_t bBase = smem_u + ST * ASZ + buf * BSZ;

        #pragma unroll
        for (int ks = 0; ks < BK; ks += 16) {
            unsigned a[MT][4], b[NTL/2][4];
            #pragma unroll
            for (int mt = 0; mt < MT; mt++)
                ldm4(a[mt], aBase + aoff[mt] + ks * 2);
            #pragma unroll
            for (int p = 0; p < NTL/2; p++)
                ldm4(b[p], bBase + boff[p] + ks * 2);
            #pragma unroll
            for (int mt = 0; mt < MT; mt++)
                #pragma unroll
                for (int p = 0; p < NTL/2; p++) {
                    mma16(c[mt][2*p],   a[mt], &b[p][0]);
                    mma16(c[mt][2*p+1], a[mt], &b[p][2]);
                }
        }
    }

    auto ep = [&](float v, int n, long m) -> float {
        if constexpr (MODE == 0) {
            v += (bias2 && n >= 1024) ? bias2[n - 1024] : bias[n];
        } else if constexpr (MODE == 1) {
            v += bias[n] + res[m * ldres + n];
            v = (v - bnm[n]) * rsqrtf(bnv[n] + 1e-5f) * bng[n] + bnb[n];
        } else if constexpr (MODE == 2) {
            v += bias[n];
            v = 0.5f * v * (1.0f + erff(v * 0.70710678118654752f));
            v = (v - bnm[n]) * rsqrtf(bnv[n] + 1e-5f) * bng[n] + bnb[n];
        }
        return v;
    };

    #pragma unroll
    for (int mt = 0; mt < MT; mt++) {
        #pragma unroll
        for (int nt = 0; nt < NTL; nt++) {
            const int row = m0 + wm * WM + mt * 16 + g;
            const int col = n0 + wn * WN + nt * 8 + 2 * t;
            float v00 = ep(c[mt][nt][0], col,     row);
            float v01 = ep(c[mt][nt][1], col + 1, row);
            float v10 = ep(c[mt][nt][2], col,     row + 8);
            float v11 = ep(c[mt][nt][3], col + 1, row + 8);
            if constexpr (OUTH) {
                __half* Ch = (__half*)Cv;
                *(__half2*)(Ch + (long)(row    ) * ldc + col) = __floats2half2_rn(v00, v01);
                *(__half2*)(Ch + (long)(row + 8) * ldc + col) = __floats2half2_rn(v10, v11);
            } else {
                float* Cf = (float*)Cv;
                *(float2*)(Cf + (long)(row    ) * ldc + col) = make_float2(v00, v01);
                *(float2*)(Cf + (long)(row + 8) * ldc + col) = make_float2(v10, v11);
            }
        }
    }
}

// ---------------- fused flash attention: scores+mask+softmax+attn@V ----------
// Block: 64 query rows x one (b,h). 8 warps = 4 row-groups x 2 col-halves.
// Two-pass: pass 1 (it 0-7) online row max/sum over K chunks; pass 2 (it 8-15)
// recompute scores, write normalized attn fp32 to d_out AND accumulate
// ctx = attn @ V in registers (score C-fragments reused as PV A-fragments).
// K/V stream through 2-deep cp.async rings (V only loaded for pass 2).
__global__ void __launch_bounds__(256)
sf3_k(const __half* __restrict__ q,
      const __half* __restrict__ kv,
      const __half* __restrict__ vt,
      float* __restrict__ outa,
      __half* __restrict__ ctx,
      const int* __restrict__ mask)
{
    constexpr int ROWS = 64;
    constexpr int QSZ  = ROWS * 144;       // 9216
    constexpr int KSZ  = 128 * 144;        // 18432
    constexpr int VSZ  = 64 * 272;         // 17408 (64 dk rows x 128 cols, stride 136 halves)

    extern __shared__ char smem[];
    const uint32_t smem_u = (uint32_t)__cvta_generic_to_shared(smem);
    const uint32_t qBase = smem_u;
    const uint32_t kBase = smem_u + QSZ;
    const uint32_t vBase = smem_u + QSZ + 2 * KSZ;
    float* sM  = (float*)(smem + QSZ + 2 * KSZ + 2 * VSZ);   // [64][2]
    float* sSm = sM + 128;                                    // [64][2]
    float* fM  = sSm + 128;                                   // [64]
    float* fI  = fM + 64;                                     // [64]
    float* xch = (float*)(smem + QSZ + 2 * KSZ);              // aliases V ring post-loop

    const int z  = blockIdx.z;
    const int zb = z >> 4;
    const int zh = z & 15;
    const int m0r = blockIdx.x * ROWS;

    const int tid = threadIdx.x;
    const int warp = tid >> 5, lane = tid & 31;
    const int wm = warp >> 1, wn = warp & 1;        // 4 x 2 warps: WM=16, WN=64
    const int g  = lane >> 2,  t = lane & 3;

    const int arow  = (lane & 7) | (((lane >> 3) & 1) << 3);
    const int akofs = (lane >> 4) << 3;
    const int brow  = ((lane >> 4) << 3) | (lane & 7);
    const int bkofs = ((lane >> 3) & 1) << 3;
    const uint32_t aoff = ((wm * 16 + arow) * 72 + akofs) * 2;
    uint32_t boff[4], vboff[4];
    #pragma unroll
    for (int p = 0; p < 4; p++) {
        boff[p]  = ((wn * 64 + p * 16 + brow) * 72 + bkofs) * 2;
        vboff[p] = ((p * 16 + brow) * 136 + bkofs) * 2;
    }

    auto load_stage = [&](int it) {
        const int nc = it & 7;
        const int buf = it & 1;
        #pragma unroll
        for (int s = tid; s < 1024; s += 256) {
            int row = s >> 3, seg = s & 7;
            cpa16u(kBase + buf * KSZ + row * 144 + seg * 16,
                   kv + (long)(zb * SS + nc * 128 + row) * 2048 + zh * 64 + seg * 8);
        }
        if (it >= 8) {
            #pragma unroll
            for (int s = tid; s < 1024; s += 256) {
                int row = s >> 4, seg = s & 15;
                cpa16u(vBase + buf * VSZ + row * 272 + seg * 16,
                       vt + ((long)z * 64 + row) * SS + nc * 128 + seg * 8);
            }
        }
    };

    // prologue: q + chunk 0 in group 0
    #pragma unroll
    for (int s = tid; s < ROWS * 8; s += 256) {
        int row = s >> 3, seg = s & 7;
        cpa16u(qBase + row * 144 + seg * 16,
               q + (long)(zb * SS + m0r + row) * DD + zh * 64 + seg * 8);
    }
    load_stage(0);
    cp_commit();

    float mrun0 = -1e30f, mrun1 = -1e30f, srun0 = 0.0f, srun1 = 0.0f;
    float ctxacc[8][4];
    #pragma unroll
    for (int j = 0; j < 8; j++)
        #pragma unroll
        for (int e = 0; e < 4; e++) ctxacc[j][e] = 0.0f;
    const long zbase = (long)z * SS * SS;

    for (int it = 0; it < 16; ++it) {
        const int nc = it & 7;
        if (it + 1 < 16) load_stage(it + 1);
        cp_commit();
        cp_wait<1>();
        __syncthreads();

        // ---- cross-warp softmax stats reduction between passes ----
        if (it == 8) {
            if (t == 0) {
                const int r0 = wm * 16 + g;
                sM [r0 * 2 + wn] = mrun0;  sSm[r0 * 2 + wn] = srun0;
                sM [(r0+8) * 2 + wn] = mrun1;  sSm[(r0+8) * 2 + wn] = srun1;
            }
            __syncthreads();
            if (tid < 64) {
                float m = fmaxf(sM[tid*2], sM[tid*2+1]);
                float s = sSm[tid*2]   * __expf(sM[tid*2]   - m)
                        + sSm[tid*2+1] * __expf(sM[tid*2+1] - m);
                fM[tid] = m; fI[tid] = 1.0f / s;
            }
            __syncthreads();
        }

        const uint32_t kb = kBase + (it & 1) * KSZ;
        float c[8][4];
        #pragma unroll
        for (int i = 0; i < 8; i++)
            #pragma unroll
            for (int e = 0; e < 4; e++) c[i][e] = 0.0f;

        #pragma unroll
        for (int ks = 0; ks < 64; ks += 16) {
            unsigned a[4], b[4][4];
            ldm4(a, qBase + aoff + ks * 2);
            #pragma unroll
            for (int p = 0; p < 4; p++)
                ldm4(b[p], kb + boff[p] + ks * 2);
            #pragma unroll
            for (int p = 0; p < 4; p++) {
                mma16(c[2*p],   a, &b[p][0]);
                mma16(c[2*p+1], a, &b[p][2]);
            }
        }

        // mask + scale in place
        #pragma unroll
        for (int j = 0; j < 8; j++) {
            const int col = nc * 128 + wn * 64 + j * 8 + 2 * t;
            const int mA = mask[zb * SS + col];
            const int mB = mask[zb * SS + col + 1];
            c[j][0] = mA ? c[j][0] * 0.125f : -1e9f;
            c[j][1] = mB ? c[j][1] * 0.125f : -1e9f;
            c[j][2] = mA ? c[j][2] * 0.125f : -1e9f;
            c[j][3] = mB ? c[j][3] * 0.125f : -1e9f;
        }

        if (it < 8) {
            // ---- pass 1: online max/sum (rows g and g+8) ----
            float m0c = -1e30f, m1c = -1e30f;
            #pragma unroll
            for (int j = 0; j < 8; j++) {
                m0c = fmaxf(m0c, fmaxf(c[j][0], c[j][1]));
                m1c = fmaxf(m1c, fmaxf(c[j][2], c[j][3]));
            }
            #pragma unroll
            for (int o = 1; o <= 2; o <<= 1) {
                m0c = fmaxf(m0c, __shfl_xor_sync(0xffffffffu, m0c, o));
                m1c = fmaxf(m1c, __shfl_xor_sync(0xffffffffu, m1c, o));
            }
            const float n0 = fmaxf(mrun0, m0c), n1 = fmaxf(mrun1, m1c);
            float s0 = 0.0f, s1 = 0.0f;
            #pragma unroll
            for (int j = 0; j < 8; j++) {
                s0 += __expf(c[j][0] - n0) + __expf(c[j][1] - n0);
                s1 += __expf(c[j][2] - n1) + __expf(c[j][3] - n1);
            }
            #pragma unroll
            for (int o = 1; o <= 2; o <<= 1) {
                s0 += __shfl_xor_sync(0xffffffffu, s0, o);
                s1 += __shfl_xor_sync(0xffffffffu, s1, o);
            }
            srun0 = srun0 * __expf(mrun0 - n0) + s0; mrun0 = n0;
            srun1 = srun1 * __expf(mrun1 - n1) + s1; mrun1 = n1;
        } else {
            // ---- pass 2: normalize, write attn fp32, and accumulate ctx ----
            const int r0 = wm * 16 + g, r1 = r0 + 8;
            const float fm0 = fM[r0], fi0 = fI[r0];
            const float fm1 = fM[r1], fi1 = fI[r1];
            const long b0r = zbase + (long)(m0r + r0) * SS;
            const long b1r = zbase + (long)(m0r + r1) * SS;
            unsigned wv[8][2];
            #pragma unroll
            for (int j = 0; j < 8; j++) {
                const int col = nc * 128 + wn * 64 + j * 8 + 2 * t;
                float w00 = __expf(c[j][0] - fm0) * fi0;
                float w01 = __expf(c[j][1] - fm0) * fi0;
                float w10 = __expf(c[j][2] - fm1) * fi1;
                float w11 = __expf(c[j][3] - fm1) * fi1;
                *(float2*)&outa[b0r + col] = make_float2(w00, w01);
                *(float2*)&outa[b1r + col] = make_float2(w10, w11);
                wv[j][0] = packh2(w00, w01);   // row g
                wv[j][1] = packh2(w10, w11);   // row g+8
            }
            // PV: ctx += w[16 x 64cols] @ V[64cols x 64dk]
            const uint32_t vb = vBase + (it & 1) * VSZ;
            const uint32_t vkofs = (uint32_t)(wn * 64) * 2;
            #pragma unroll
            for (int s = 0; s < 4; s++) {
                unsigned a[4] = { wv[2*s][0], wv[2*s][1], wv[2*s+1][0], wv[2*s+1][1] };
                #pragma unroll
                for (int p = 0; p < 4; p++) {
                    unsigned bv[4];
                    ldm4(bv, vb + vboff[p] + vkofs + s * 32);
                    mma16(ctxacc[2*p],   a, &bv[0]);
                    mma16(ctxacc[2*p+1], a, &bv[2]);
                }
            }
        }
        __syncthreads();   // all warps done with buffers before next overwrite
    }

    // ---- reduce ctx across the two column-half warps and store ----
    if (wn == 1) {
        float* dst = xch + (wm * 32 + lane) * 32;
        #pragma unroll
        for (int j = 0; j < 8; j++)
            #pragma unroll
            for (int e = 0; e < 4; e++) dst[j * 4 + e] = ctxacc[j][e];
    }
    __syncthreads();
    if (wn == 0) {
        const float* src = xch + (wm * 32 + lane) * 32;
        const int r0 = m0r + wm * 16 + g, r1 = r0 + 8;
        #pragma unroll
        for (int j = 0; j < 8; j++) {
            float v0 = ctxacc[j][0] + src[j*4+0];
            float v1 = ctxacc[j][1] + src[j*4+1];
            float v2 = ctxacc[j][2] + src[j*4+2];
            float v3 = ctxacc[j][3] + src[j*4+3];
            const int dk = j * 8 + 2 * t;
            *(__half2*)(ctx + (long)(zb * SS + r0) * DD + zh * 64 + dk) = __floats2half2_rn(v0, v1);
            *(__half2*)(ctx + (long)(zb * SS + r1) * DD + zh * 64 + dk) = __floats2half2_rn(v2, v3);
        }
    }
}

// ---------------- float -> half convert (vectorized) -------------------------
__global__ void __launch_bounds__(256)
cvt_k(const float* __restrict__ in, __half* __restrict__ out, int n4)
{
    int i = blockIdx.x * 256 + threadIdx.x;
    if (i < n4) {
        float4 v = ((const float4*)in)[i];
        ((__half2*)out)[2*i]   = __floats2half2_rn(v.x, v.y);
        ((__half2*)out)[2*i+1] = __floats2half2_rn(v.z, v.w);
    }
}

// ---------------- V transpose: kv[token][1024+h*64+dk] -> vt[b,h][dk][s] -----
__global__ void __launch_bounds__(256)
vt_k(const __half* __restrict__ v, int ldv, __half* __restrict__ vt)
{
    __shared__ __half tile[64][72];
    const int z = blockIdx.z;
    const int b = z >> 4, h = z & 15;
    const int s0 = blockIdx.x * 64;
    const int tid = threadIdx.x;

    #pragma unroll
    for (int p = 0; p < 2; p++) {
        int r   = p * 32 + (tid >> 3);
        int seg = tid & 7;
        uint4 d = *(const uint4*)(v + ((long)(b * SS + s0 + r)) * ldv + h * 64 + seg * 8);
        *(uint4*)&tile[r][seg * 8] = d;
    }
    __syncthreads();
    #pragma unroll
    for (int p = 0; p < 2; p++) {
        int c   = p * 32 + (tid >> 3);
        int seg = tid & 7;
        __half tmp[8];
        #pragma unroll
        for (int j = 0; j < 8; j++) tmp[j] = tile[seg * 8 + j][c];
        *(uint4*)(vt + ((long)z * 64 + c) * SS + s0 + seg * 8) = *(uint4*)tmp;
    }
}

// ---------------- LayerNorm over D=1024; half output -------------------------
__global__ void __launch_bounds__(256)
ln_k(const float* __restrict__ x, const float* __restrict__ g,
     const float* __restrict__ b, __half* __restrict__ o)
{
    __shared__ float red[8];
    const long row = blockIdx.x;
    const int  t = threadIdx.x, lane = t & 31, w = t >> 5;

    float4 v = ((const float4*)(x + row * DD))[t];
    float s = v.x + v.y + v.z + v.w;
    #pragma unroll
    for (int off = 16; off; off >>= 1) s += __shfl_down_sync(0xffffffffu, s, off);
    if (!lane) red[w] = s;
    __syncthreads();
    if (t == 0) { float a = 0.f; for (int i = 0; i < 8; i++) a += red[i]; red[0] = a; }
    __syncthreads();
    const float mu = red[0] * (1.0f / DD);
    __syncthreads();

    float d0 = v.x - mu, d1 = v.y - mu, d2 = v.z - mu, d3 = v.w - mu;
    float sq = d0*d0 + d1*d1 + d2*d2 + d3*d3;
    #pragma unroll
    for (int off = 16; off; off >>= 1) sq += __shfl_down_sync(0xffffffffu, sq, off);
    if (!lane) red[w] = sq;
    __syncthreads();
    if (t == 0) { float a = 0.f; for (int i = 0; i < 8; i++) a += red[i]; red[0] = a; }
    __syncthreads();
    const float rs = rsqrtf(red[0] * (1.0f / DD) + 1e-5f);

    float4 g4 = ((const float4*)g)[t];
    float4 b4 = ((const float4*)b)[t];
    __half2* op = (__half2*)(o + row * DD);
    op[2*t]   = __floats2half2_rn(d0 * rs * g4.x + b4.x, d1 * rs * g4.y + b4.y);
    op[2*t+1] = __floats2half2_rn(d2 * rs * g4.z + b4.z, d3 * rs * g4.w + b4.w);
}

// ---------------- host orchestration ----------------------------------------
extern "C" void kernel_launch(void* const* d_in, const int* in_sizes, int n_in,
                              void* d_out, int out_size)
{
    const float* x    = (const float*)d_in[0];
    const int*   mask = (const int*)  d_in[1];
    const float* Wq = (const float*)d_in[2];  const float* bq = (const float*)d_in[3];
    const float* Wk = (const float*)d_in[4];  const float* bk = (const float*)d_in[5];
    const float* Wv = (const float*)d_in[6];  const float* bv = (const float*)d_in[7];
    const float* Wo = (const float*)d_in[8];  const float* bo = (const float*)d_in[9];
    const float* lag = (const float*)d_in[10]; const float* lab = (const float*)d_in[11];
    const float* W1 = (const float*)d_in[12]; const float* b1 = (const float*)d_in[13];
    const float* W2 = (const float*)d_in[14]; const float* b2 = (const float*)d_in[15];
    const float* lfg = (const float*)d_in[16]; const float* lfb = (const float*)d_in[17];
    const float* bnffg = (const float*)d_in[18]; const float* bnffb = (const float*)d_in[19];
    const float* bnffm = (const float*)d_in[20]; const float* bnffv = (const float*)d_in[21];
    const float* bn1g = (const float*)d_in[22]; const float* bn1b = (const float*)d_in[23];
    const float* bn1m = (const float*)d_in[24]; const float* bn1v = (const float*)d_in[25];
    const float* bn2g = (const float*)d_in[26]; const float* bn2b = (const float*)d_in[27];
    const float* bn2m = (const float*)d_in[28]; const float* bn2v = (const float*)d_in[29];

    __half *xq, *xr, *q, *kv, *vt, *ctx, *h, *w;
    float *x1;
    cudaGetSymbolAddress((void**)&xq,  g_xq);
    cudaGetSymbolAddress((void**)&xr,  g_xr);
    cudaGetSymbolAddress((void**)&q,   g_q);
    cudaGetSymbolAddress((void**)&kv,  g_kv);
    cudaGetSymbolAddress((void**)&vt,  g_vt);
    cudaGetSymbolAddress((void**)&ctx, g_ctx);
    cudaGetSymbolAddress((void**)&x1,  g_x1);
    cudaGetSymbolAddress((void**)&h,   g_h);
    cudaGetSymbolAddress((void**)&w,   g_w);

    __half* cWq = w;
    __half* cWk = w + 1*1024*1024;     // cWk..cWv contiguous = fused KV weight
    __half* cWv = w + 2*1024*1024;
    __half* cWo = w + 3*1024*1024;
    __half* cW1 = w + 4*1024*1024;
    __half* cW2 = w + 8*1024*1024;

    float* outx = (float*)d_out;                    // [B,S,D]
    float* outa = outx + (long)NTOK * DD;           // [B,H,S,S]

    constexpr int SM_B   = 4 * (128*80 + 256*80);               // 122880 B (big NT GEMMs)
    constexpr int SM_SF3 = 64*144 + 2*128*144 + 2*64*272 + 1536; // 82432 B (flash attn)

    //                 BM  BN  WM WN ST  MODE OUTH
    auto* kP  = gemm_h<128,256,64,64,4,  0,   true >;  // q / kv -> half
    auto* kR  = gemm_h<128,256,64,64,4,  1,   false>;  // O-proj / W2 -> fp32
    auto* kG  = gemm_h<128,256,64,64,4,  2,   true >;  // W1 -> h half
    cudaFuncSetAttribute((const void*)kP,  cudaFuncAttributeMaxDynamicSharedMemorySize, SM_B);
    cudaFuncSetAttribute((const void*)kR,  cudaFuncAttributeMaxDynamicSharedMemorySize, SM_B);
    cudaFuncSetAttribute((const void*)kG,  cudaFuncAttributeMaxDynamicSharedMemorySize, SM_B);
    cudaFuncSetAttribute((const void*)sf3_k, cudaFuncAttributeMaxDynamicSharedMemorySize, SM_SF3);

    // 0) convert weights + x to half
    cvt_k<<<(1024*1024/4 + 255)/256, 256>>>(Wq, cWq, 1024*1024/4);
    cvt_k<<<(1024*1024/4 + 255)/256, 256>>>(Wk, cWk, 1024*1024/4);
    cvt_k<<<(1024*1024/4 + 255)/256, 256>>>(Wv, cWv, 1024*1024/4);
    cvt_k<<<(1024*1024/4 + 255)/256, 256>>>(Wo, cWo, 1024*1024/4);
    cvt_k<<<(4*1024*1024/4 + 255)/256, 256>>>(W1, cW1, 4*1024*1024/4);
    cvt_k<<<(4*1024*1024/4 + 255)/256, 256>>>(W2, cW2, 4*1024*1024/4);
    cvt_k<<<(NTOK*DD/4 + 255)/256, 256>>>(x, xr, NTOK*DD/4);

    // 1) pre-LN for query path (half out)
    ln_k<<<NTOK, 256>>>(x, lag, lab, xq);

    // 2) q projection (N=1024) + fused kv projection (N=2048)
    dim3 gQ(DD / 256, NTOK / 128, 1);
    kP<<<gQ, 256, SM_B>>>(xq, DD, cWq, DD, q, DD, DD,
        bq, nullptr, nullptr,0, nullptr,nullptr,nullptr,nullptr);
    dim3 gKV(2048 / 256, NTOK / 128, 1);
    kP<<<gKV, 256, SM_B>>>(xr, DD, cWk, DD, kv, 2048, DD,
        bk, bv, nullptr,0, nullptr,nullptr,nullptr,nullptr);

    // 2b) transpose V part of kv: [s, dk] -> [dk, s] per (b,h)
    dim3 gV(SS / 64, 1, BB * HH);
    vt_k<<<gV, 256>>>(kv + 1024, 2048, vt);

    // 3-5) fused scores + mask + softmax + attn@V (flash, two-pass)
    dim3 gSF(SS / 64, 1, BB * HH);
    sf3_k<<<gSF, 256, SM_SF3>>>(q, kv, vt, outa, ctx, mask);

    // 6) O projection + residual(x) + bn1 -> x1 (fp32)
    dim3 gO(DD / 256, NTOK / 128, 1);
    kR<<<gO, 256, SM_B>>>(ctx, DD, cWo, DD, x1, DD, DD,
        bo, nullptr, x, DD, bn1g,bn1b,bn1m,bn1v);

    // 7) FFN pre-LN (half out)
    ln_k<<<NTOK, 256>>>(x1, lfg, lfb, xq);

    // 8) h = bnff(gelu(xn W1^T + b1)) -> half  M=8192 N=4096 K=1024
    dim3 g1(DF / 256, NTOK / 128, 1);
    kG<<<g1, 256, SM_B>>>(xq, DD, cW1, DD, h, DF, DD,
        b1, nullptr, nullptr,0, bnffg,bnffb,bnffm,bnffv);

    // 9) out_x = bn2(h W2^T + b2 + x1)  M=8192 N=1024 K=4096
    dim3 g2(DD / 256, NTOK / 128, 1);
    kR<<<g2, 256, SM_B>>>(h, DF, cW2, DF, outx, DD, DF,
        b2, nullptr, x1, DD, bn2g,bn2b,bn2m,bn2v);
}

// round 15
// speedup vs baseline: 1.1188x; 1.0156x over previous
#include <cuda_runtime.h>
#include <cuda_fp16.h>
#include <math.h>
#include <stdint.h>

#define BB   8
#define SS   1024
#define DD   1024
#define HH   16
#define DKK  64
#define DF   4096
#define NTOK (BB*SS)        // 8192 tokens

// ---------------- scratch (static device globals; no allocation) ------------
__device__ __half g_xq[NTOK*DD];       // LN output (half), both LNs
__device__ __half g_xr[NTOK*DD];       // x as half
__device__ __half g_q [NTOK*DD];
__device__ __half g_kv[NTOK*2048];     // fused K|V: [token][0:1024)=k, [1024:2048)=v
__device__ __half g_vt[NTOK*DD];       // [b,h][dk][token] transposed V
__device__ __half g_ctx[NTOK*DD];
__device__ float  g_x1[NTOK*DD];       // after bn1 (exact fp32)
__device__ __half g_h [NTOK*DF];       // FFN hidden
__device__ __half g_w [12*1024*1024];  // half weights: Wq Wk Wv Wo | W1 | W2

// ---------------- helpers ----------------------------------------------------
__device__ __forceinline__ void cpa16(void* s, const void* g) {
    unsigned sa = (unsigned)__cvta_generic_to_shared(s);
    asm volatile("cp.async.cg.shared.global [%0], [%1], 16;" :: "r"(sa), "l"(g));
}
__device__ __forceinline__ void cpa16u(uint32_t sa, const void* g) {
    asm volatile("cp.async.cg.shared.global [%0], [%1], 16;" :: "r"(sa), "l"(g));
}
__device__ __forceinline__ void cp_commit() { asm volatile("cp.async.commit_group;"); }
template<int N> __device__ __forceinline__ void cp_wait() {
    asm volatile("cp.async.wait_group %0;" :: "n"(N));
}
__device__ __forceinline__ void mma16(float* c, const unsigned* a, const unsigned* b) {
    asm volatile(
        "mma.sync.aligned.m16n8k16.row.col.f32.f16.f16.f32 "
        "{%0,%1,%2,%3}, {%4,%5,%6,%7}, {%8,%9}, {%0,%1,%2,%3};"
        : "+f"(c[0]), "+f"(c[1]), "+f"(c[2]), "+f"(c[3])
        : "r"(a[0]), "r"(a[1]), "r"(a[2]), "r"(a[3]), "r"(b[0]), "r"(b[1]));
}
__device__ __forceinline__ void ldm4(unsigned* r, uint32_t addr) {
    asm volatile("ldmatrix.sync.aligned.m8n8.x4.shared.b16 {%0,%1,%2,%3}, [%4];"
                 : "=r"(r[0]), "=r"(r[1]), "=r"(r[2]), "=r"(r[3]) : "r"(addr));
}
__device__ __forceinline__ unsigned packh2(float lo, float hi) {
    __half2 h = __floats2half2_rn(lo, hi);
    return *reinterpret_cast<unsigned*>(&h);
}
__device__ __forceinline__ float ex2f(float x) {
    float r;
    asm("ex2.approx.f32 %0, %1;" : "=f"(r) : "f"(x));
    return r;
}

// ---------------- fp16 tensor-core GEMM (ST-stage cp.async + ldmatrix, NT) ---
// C[M,N] = A[M,K] * B[N,K]^T + epilogue. A,B half, K-major.
// bias2: if non-null, cols >=1024 use bias2[n-1024] (fused KV projection).
// MODE: 0 bias | 1 bias+res+BN | 2 bias+GELU+BN
template<int BM,int BN,int WM,int WN,int ST,int MODE,bool OUTH>
__global__ void __launch_bounds__(256)
gemm_h(const __half* __restrict__ A, int lda,
       const __half* __restrict__ B, int ldb,
       void* __restrict__ Cv, int ldc,
       int K,
       const float* __restrict__ bias, const float* __restrict__ bias2,
       const float* __restrict__ res, int ldres,
       const float* __restrict__ bng, const float* __restrict__ bnb,
       const float* __restrict__ bnm, const float* __restrict__ bnv)
{
    constexpr int BK  = 32;
    constexpr int ASZ = BM * 80;
    constexpr int BSZ = BN * 80;

    extern __shared__ char smem[];
    const uint32_t smem_u = (uint32_t)__cvta_generic_to_shared(smem);

    const int tid = threadIdx.x;
    const int m0  = blockIdx.y * BM;
    const int n0  = blockIdx.x * BN;

    const int warp = tid >> 5, lane = tid & 31;
    constexpr int WGN = BN / WN;
    const int wm = warp / WGN, wn = warp % WGN;
    const int g  = lane >> 2,  t  = lane & 3;
    constexpr int MT  = WM / 16;
    constexpr int NTL = WN / 8;

    const int arow  = (lane & 7) | (((lane >> 3) & 1) << 3);
    const int akofs = (lane >> 4) << 3;
    const int brow  = ((lane >> 4) << 3) | (lane & 7);
    const int bkofs = ((lane >> 3) & 1) << 3;
    uint32_t aoff[MT], boff[NTL/2];
    #pragma unroll
    for (int mt = 0; mt < MT; mt++)
        aoff[mt] = ((wm * WM + mt * 16 + arow) * 40 + akofs) * 2;
    #pragma unroll
    for (int p = 0; p < NTL/2; p++)
        boff[p] = ((wn * WN + p * 16 + brow) * 40 + bkofs) * 2;

    float c[MT][NTL][4];
    #pragma unroll
    for (int i = 0; i < MT; i++)
        #pragma unroll
        for (int j = 0; j < NTL; j++)
            #pragma unroll
            for (int e = 0; e < 4; e++) c[i][j][e] = 0.0f;

    const int iters = K / BK;

    auto load_stage = [&](int it, int buf) {
        const int k0 = it * BK;
        char* dA = smem + buf * ASZ;
        char* dB = smem + ST * ASZ + buf * BSZ;
        #pragma unroll
        for (int s = tid; s < BM * 4; s += 256) {
            int row = s >> 2, seg = s & 3;
            cpa16(dA + row * 80 + seg * 16,
                  A + (long)(m0 + row) * lda + k0 + seg * 8);
        }
        #pragma unroll
        for (int s = tid; s < BN * 4; s += 256) {
            int row = s >> 2, seg = s & 3;
            cpa16(dB + row * 80 + seg * 16,
                  B + (long)(n0 + row) * ldb + k0 + seg * 8);
        }
    };

    #pragma unroll
    for (int s = 0; s < ST - 1; s++) {
        if (s < iters) load_stage(s, s);
        cp_commit();
    }

    for (int it = 0; it < iters; ++it) {
        cp_wait<ST - 2>();
        __syncthreads();

        if (it + ST - 1 < iters) load_stage(it + ST - 1, (it + ST - 1) % ST);
        cp_commit();

        const int buf = it % ST;
        const uint32_t aBase = smem_u + buf * ASZ;
        const uint32_t bBase = smem_u + ST * ASZ + buf * BSZ;

        #pragma unroll
        for (int ks = 0; ks < BK; ks += 16) {
            unsigned a[MT][4], b[NTL/2][4];
            #pragma unroll
            for (int mt = 0; mt < MT; mt++)
                ldm4(a[mt], aBase + aoff[mt] + ks * 2);
            #pragma unroll
            for (int p = 0; p < NTL/2; p++)
                ldm4(b[p], bBase + boff[p] + ks * 2);
            #pragma unroll
            for (int mt = 0; mt < MT; mt++)
                #pragma unroll
                for (int p = 0; p < NTL/2; p++) {
                    mma16(c[mt][2*p],   a[mt], &b[p][0]);
                    mma16(c[mt][2*p+1], a[mt], &b[p][2]);
                }
        }
    }

    auto ep = [&](float v, int n, long m) -> float {
        if constexpr (MODE == 0) {
            v += (bias2 && n >= 1024) ? bias2[n - 1024] : bias[n];
        } else if constexpr (MODE == 1) {
            v += bias[n] + res[m * ldres + n];
            v = (v - bnm[n]) * rsqrtf(bnv[n] + 1e-5f) * bng[n] + bnb[n];
        } else if constexpr (MODE == 2) {
            v += bias[n];
            v = 0.5f * v * (1.0f + erff(v * 0.70710678118654752f));
            v = (v - bnm[n]) * rsqrtf(bnv[n] + 1e-5f) * bng[n] + bnb[n];
        }
        return v;
    };

    #pragma unroll
    for (int mt = 0; mt < MT; mt++) {
        #pragma unroll
        for (int nt = 0; nt < NTL; nt++) {
            const int row = m0 + wm * WM + mt * 16 + g;
            const int col = n0 + wn * WN + nt * 8 + 2 * t;
            float v00 = ep(c[mt][nt][0], col,     row);
            float v01 = ep(c[mt][nt][1], col + 1, row);
            float v10 = ep(c[mt][nt][2], col,     row + 8);
            float v11 = ep(c[mt][nt][3], col + 1, row + 8);
            if constexpr (OUTH) {
                __half* Ch = (__half*)Cv;
                *(__half2*)(Ch + (long)(row    ) * ldc + col) = __floats2half2_rn(v00, v01);
                *(__half2*)(Ch + (long)(row + 8) * ldc + col) = __floats2half2_rn(v10, v11);
            } else {
                float* Cf = (float*)Cv;
                *(float2*)(Cf + (long)(row    ) * ldc + col) = make_float2(v00, v01);
                *(float2*)(Cf + (long)(row + 8) * ldc + col) = make_float2(v10, v11);
            }
        }
    }
}

// ---------------- fused flash attention: scores+mask+softmax+attn@V ----------
// Block: 64 query rows x one (b,h). 8 warps = 4 row-groups x 2 col-halves.
// Log2-domain softmax (SCL = 0.125*log2e folded into scores; bare ex2).
// Mask precomputed into a 4KB smem addend table. attn stores use __stcs.
__global__ void __launch_bounds__(256)
sf3_k(const __half* __restrict__ q,
      const __half* __restrict__ kv,
      const __half* __restrict__ vt,
      float* __restrict__ outa,
      __half* __restrict__ ctx,
      const int* __restrict__ mask)
{
    constexpr int ROWS = 64;
    constexpr int QSZ  = ROWS * 144;       // 9216
    constexpr int KSZ  = 128 * 144;        // 18432
    constexpr int VSZ  = 64 * 272;         // 17408
    constexpr float SCL = 0.18033688011112042f;   // 0.125 * log2(e)

    extern __shared__ char smem[];
    const uint32_t smem_u = (uint32_t)__cvta_generic_to_shared(smem);
    const uint32_t qBase = smem_u;
    const uint32_t kBase = smem_u + QSZ;
    const uint32_t vBase = smem_u + QSZ + 2 * KSZ;
    float* sM   = (float*)(smem + QSZ + 2 * KSZ + 2 * VSZ);  // [64][2]
    float* sSm  = sM + 128;                                   // [64][2]
    float* fM   = sSm + 128;                                  // [64]
    float* fI   = fM + 64;                                    // [64]
    float* madd = fI + 64;                                    // [1024]
    float* xch  = (float*)(smem + QSZ + 2 * KSZ);             // aliases V ring post-loop

    const int z  = blockIdx.z;
    const int zb = z >> 4;
    const int zh = z & 15;
    const int m0r = blockIdx.x * ROWS;

    const int tid = threadIdx.x;
    const int warp = tid >> 5, lane = tid & 31;
    const int wm = warp >> 1, wn = warp & 1;        // 4 x 2 warps: WM=16, WN=64
    const int g  = lane >> 2,  t = lane & 3;

    const int arow  = (lane & 7) | (((lane >> 3) & 1) << 3);
    const int akofs = (lane >> 4) << 3;
    const int brow  = ((lane >> 4) << 3) | (lane & 7);
    const int bkofs = ((lane >> 3) & 1) << 3;
    const uint32_t aoff = ((wm * 16 + arow) * 72 + akofs) * 2;
    uint32_t boff[4], vboff[4];
    #pragma unroll
    for (int p = 0; p < 4; p++) {
        boff[p]  = ((wn * 64 + p * 16 + brow) * 72 + bkofs) * 2;
        vboff[p] = ((p * 16 + brow) * 136 + bkofs) * 2;
    }

    auto load_stage = [&](int it) {
        const int nc = it & 7;
        const int buf = it & 1;
        #pragma unroll
        for (int s = tid; s < 1024; s += 256) {
            int row = s >> 3, seg = s & 7;
            cpa16u(kBase + buf * KSZ + row * 144 + seg * 16,
                   kv + (long)(zb * SS + nc * 128 + row) * 2048 + zh * 64 + seg * 8);
        }
        if (it >= 8) {
            #pragma unroll
            for (int s = tid; s < 1024; s += 256) {
                int row = s >> 4, seg = s & 15;
                cpa16u(vBase + buf * VSZ + row * 272 + seg * 16,
                       vt + ((long)z * 64 + row) * SS + nc * 128 + seg * 8);
            }
        }
    };

    // prologue: q + chunk 0 + mask table
    #pragma unroll
    for (int s = tid; s < ROWS * 8; s += 256) {
        int row = s >> 3, seg = s & 7;
        cpa16u(qBase + row * 144 + seg * 16,
               q + (long)(zb * SS + m0r + row) * DD + zh * 64 + seg * 8);
    }
    #pragma unroll
    for (int s = tid; s < 1024; s += 256)
        madd[s] = mask[zb * SS + s] ? 0.0f : -1.4426950e9f;
    load_stage(0);
    cp_commit();

    float mrun0 = -1e30f, mrun1 = -1e30f, srun0 = 0.0f, srun1 = 0.0f;
    float ctxacc[8][4];
    #pragma unroll
    for (int j = 0; j < 8; j++)
        #pragma unroll
        for (int e = 0; e < 4; e++) ctxacc[j][e] = 0.0f;
    const long zbase = (long)z * SS * SS;

    for (int it = 0; it < 16; ++it) {
        const int nc = it & 7;
        if (it + 1 < 16) load_stage(it + 1);
        cp_commit();
        cp_wait<1>();
        __syncthreads();

        // ---- cross-warp softmax stats reduction between passes ----
        if (it == 8) {
            if (t == 0) {
                const int r0 = wm * 16 + g;
                sM [r0 * 2 + wn] = mrun0;  sSm[r0 * 2 + wn] = srun0;
                sM [(r0+8) * 2 + wn] = mrun1;  sSm[(r0+8) * 2 + wn] = srun1;
            }
            __syncthreads();
            if (tid < 64) {
                float m = fmaxf(sM[tid*2], sM[tid*2+1]);
                float s = sSm[tid*2]   * ex2f(sM[tid*2]   - m)
                        + sSm[tid*2+1] * ex2f(sM[tid*2+1] - m);
                fM[tid] = m; fI[tid] = 1.0f / s;
            }
            __syncthreads();
        }

        const uint32_t kb = kBase + (it & 1) * KSZ;
        float c[8][4];
        #pragma unroll
        for (int i = 0; i < 8; i++)
            #pragma unroll
            for (int e = 0; e < 4; e++) c[i][e] = 0.0f;

        #pragma unroll
        for (int ks = 0; ks < 64; ks += 16) {
            unsigned a[4], b[4][4];
            ldm4(a, qBase + aoff + ks * 2);
            #pragma unroll
            for (int p = 0; p < 4; p++)
                ldm4(b[p], kb + boff[p] + ks * 2);
            #pragma unroll
            for (int p = 0; p < 4; p++) {
                mma16(c[2*p],   a, &b[p][0]);
                mma16(c[2*p+1], a, &b[p][2]);
            }
        }

        // scale to log2 domain + mask addend (smem table)
        #pragma unroll
        for (int j = 0; j < 8; j++) {
            const int col = nc * 128 + wn * 64 + j * 8 + 2 * t;
            const float mA = madd[col], mB = madd[col + 1];
            c[j][0] = fmaf(c[j][0], SCL, mA);
            c[j][1] = fmaf(c[j][1], SCL, mB);
            c[j][2] = fmaf(c[j][2], SCL, mA);
            c[j][3] = fmaf(c[j][3], SCL, mB);
        }

        if (it < 8) {
            // ---- pass 1: online max/sum (rows g and g+8), log2 domain ----
            float m0c = -1e30f, m1c = -1e30f;
            #pragma unroll
            for (int j = 0; j < 8; j++) {
                m0c = fmaxf(m0c, fmaxf(c[j][0], c[j][1]));
                m1c = fmaxf(m1c, fmaxf(c[j][2], c[j][3]));
            }
            #pragma unroll
            for (int o = 1; o <= 2; o <<= 1) {
                m0c = fmaxf(m0c, __shfl_xor_sync(0xffffffffu, m0c, o));
                m1c = fmaxf(m1c, __shfl_xor_sync(0xffffffffu, m1c, o));
            }
            const float n0 = fmaxf(mrun0, m0c), n1 = fmaxf(mrun1, m1c);
            float s0 = 0.0f, s1 = 0.0f;
            #pragma unroll
            for (int j = 0; j < 8; j++) {
                s0 += ex2f(c[j][0] - n0) + ex2f(c[j][1] - n0);
                s1 += ex2f(c[j][2] - n1) + ex2f(c[j][3] - n1);
            }
            #pragma unroll
            for (int o = 1; o <= 2; o <<= 1) {
                s0 += __shfl_xor_sync(0xffffffffu, s0, o);
                s1 += __shfl_xor_sync(0xffffffffu, s1, o);
            }
            srun0 = srun0 * ex2f(mrun0 - n0) + s0; mrun0 = n0;
            srun1 = srun1 * ex2f(mrun1 - n1) + s1; mrun1 = n1;
        } else {
            // ---- pass 2: normalize, stream attn fp32, accumulate ctx ----
            const int r0 = wm * 16 + g, r1 = r0 + 8;
            const float fm0 = fM[r0], fi0 = fI[r0];
            const float fm1 = fM[r1], fi1 = fI[r1];
            const long b0r = zbase + (long)(m0r + r0) * SS;
            const long b1r = zbase + (long)(m0r + r1) * SS;
            unsigned wv[8][2];
            #pragma unroll
            for (int j = 0; j < 8; j++) {
                const int col = nc * 128 + wn * 64 + j * 8 + 2 * t;
                float w00 = ex2f(c[j][0] - fm0) * fi0;
                float w01 = ex2f(c[j][1] - fm0) * fi0;
                float w10 = ex2f(c[j][2] - fm1) * fi1;
                float w11 = ex2f(c[j][3] - fm1) * fi1;
                __stcs((float2*)&outa[b0r + col], make_float2(w00, w01));
                __stcs((float2*)&outa[b1r + col], make_float2(w10, w11));
                wv[j][0] = packh2(w00, w01);
                wv[j][1] = packh2(w10, w11);
            }
            // PV: ctx += w[16 x 64cols] @ V[64cols x 64dk]
            const uint32_t vb = vBase + (it & 1) * VSZ;
            const uint32_t vkofs = (uint32_t)(wn * 64) * 2;
            #pragma unroll
            for (int s = 0; s < 4; s++) {
                unsigned a[4] = { wv[2*s][0], wv[2*s][1], wv[2*s+1][0], wv[2*s+1][1] };
                #pragma unroll
                for (int p = 0; p < 4; p++) {
                    unsigned bv[4];
                    ldm4(bv, vb + vboff[p] + vkofs + s * 32);
                    mma16(ctxacc[2*p],   a, &bv[0]);
                    mma16(ctxacc[2*p+1], a, &bv[2]);
                }
            }
        }
        __syncthreads();
    }

    // ---- reduce ctx across the two column-half warps and store ----
    if (wn == 1) {
        float* dst = xch + (wm * 32 + lane) * 32;
        #pragma unroll
        for (int j = 0; j < 8; j++)
            #pragma unroll
            for (int e = 0; e < 4; e++) dst[j * 4 + e] = ctxacc[j][e];
    }
    __syncthreads();
    if (wn == 0) {
        const float* src = xch + (wm * 32 + lane) * 32;
        const int r0 = m0r + wm * 16 + g, r1 = r0 + 8;
        #pragma unroll
        for (int j = 0; j < 8; j++) {
            float v0 = ctxacc[j][0] + src[j*4+0];
            float v1 = ctxacc[j][1] + src[j*4+1];
            float v2 = ctxacc[j][2] + src[j*4+2];
            float v3 = ctxacc[j][3] + src[j*4+3];
            const int dk = j * 8 + 2 * t;
            *(__half2*)(ctx + (long)(zb * SS + r0) * DD + zh * 64 + dk) = __floats2half2_rn(v0, v1);
            *(__half2*)(ctx + (long)(zb * SS + r1) * DD + zh * 64 + dk) = __floats2half2_rn(v2, v3);
        }
    }
}

// ---------------- float -> half convert (vectorized) -------------------------
__global__ void __launch_bounds__(256)
cvt_k(const float* __restrict__ in, __half* __restrict__ out, int n4)
{
    int i = blockIdx.x * 256 + threadIdx.x;
    if (i < n4) {
        float4 v = ((const float4*)in)[i];
        ((__half2*)out)[2*i]   = __floats2half2_rn(v.x, v.y);
        ((__half2*)out)[2*i+1] = __floats2half2_rn(v.z, v.w);
    }
}

// ---------------- V transpose: kv[token][1024+h*64+dk] -> vt[b,h][dk][s] -----
__global__ void __launch_bounds__(256)
vt_k(const __half* __restrict__ v, int ldv, __half* __restrict__ vt)
{
    __shared__ __half tile[64][72];
    const int z = blockIdx.z;
    const int b = z >> 4, h = z & 15;
    const int s0 = blockIdx.x * 64;
    const int tid = threadIdx.x;

    #pragma unroll
    for (int p = 0; p < 2; p++) {
        int r   = p * 32 + (tid >> 3);
        int seg = tid & 7;
        uint4 d = *(const uint4*)(v + ((long)(b * SS + s0 + r)) * ldv + h * 64 + seg * 8);
        *(uint4*)&tile[r][seg * 8] = d;
    }
    __syncthreads();
    #pragma unroll
    for (int p = 0; p < 2; p++) {
        int c   = p * 32 + (tid >> 3);
        int seg = tid & 7;
        __half tmp[8];
        #pragma unroll
        for (int j = 0; j < 8; j++) tmp[j] = tile[seg * 8 + j][c];
        *(uint4*)(vt + ((long)z * 64 + c) * SS + s0 + seg * 8) = *(uint4*)tmp;
    }
}

// ---------------- LayerNorm over D=1024; half output -------------------------
__global__ void __launch_bounds__(256)
ln_k(const float* __restrict__ x, const float* __restrict__ g,
     const float* __restrict__ b, __half* __restrict__ o)
{
    __shared__ float red[8];
    const long row = blockIdx.x;
    const int  t = threadIdx.x, lane = t & 31, w = t >> 5;

    float4 v = ((const float4*)(x + row * DD))[t];
    float s = v.x + v.y + v.z + v.w;
    #pragma unroll
    for (int off = 16; off; off >>= 1) s += __shfl_down_sync(0xffffffffu, s, off);
    if (!lane) red[w] = s;
    __syncthreads();
    if (t == 0) { float a = 0.f; for (int i = 0; i < 8; i++) a += red[i]; red[0] = a; }
    __syncthreads();
    const float mu = red[0] * (1.0f / DD);
    __syncthreads();

    float d0 = v.x - mu, d1 = v.y - mu, d2 = v.z - mu, d3 = v.w - mu;
    float sq = d0*d0 + d1*d1 + d2*d2 + d3*d3;
    #pragma unroll
    for (int off = 16; off; off >>= 1) sq += __shfl_down_sync(0xffffffffu, sq, off);
    if (!lane) red[w] = sq;
    __syncthreads();
    if (t == 0) { float a = 0.f; for (int i = 0; i < 8; i++) a += red[i]; red[0] = a; }
    __syncthreads();
    const float rs = rsqrtf(red[0] * (1.0f / DD) + 1e-5f);

    float4 g4 = ((const float4*)g)[t];
    float4 b4 = ((const float4*)b)[t];
    __half2* op = (__half2*)(o + row * DD);
    op[2*t]   = __floats2half2_rn(d0 * rs * g4.x + b4.x, d1 * rs * g4.y + b4.y);
    op[2*t+1] = __floats2half2_rn(d2 * rs * g4.z + b4.z, d3 * rs * g4.w + b4.w);
}

// ---------------- host orchestration ----------------------------------------
extern "C" void kernel_launch(void* const* d_in, const int* in_sizes, int n_in,
                              void* d_out, int out_size)
{
    const float* x    = (const float*)d_in[0];
    const int*   mask = (const int*)  d_in[1];
    const float* Wq = (const float*)d_in[2];  const float* bq = (const float*)d_in[3];
    const float* Wk = (const float*)d_in[4];  const float* bk = (const float*)d_in[5];
    const float* Wv = (const float*)d_in[6];  const float* bv = (const float*)d_in[7];
    const float* Wo = (const float*)d_in[8];  const float* bo = (const float*)d_in[9];
    const float* lag = (const float*)d_in[10]; const float* lab = (const float*)d_in[11];
    const float* W1 = (const float*)d_in[12]; const float* b1 = (const float*)d_in[13];
    const float* W2 = (const float*)d_in[14]; const float* b2 = (const float*)d_in[15];
    const float* lfg = (const float*)d_in[16]; const float* lfb = (const float*)d_in[17];
    const float* bnffg = (const float*)d_in[18]; const float* bnffb = (const float*)d_in[19];
    const float* bnffm = (const float*)d_in[20]; const float* bnffv = (const float*)d_in[21];
    const float* bn1g = (const float*)d_in[22]; const float* bn1b = (const float*)d_in[23];
    const float* bn1m = (const float*)d_in[24]; const float* bn1v = (const float*)d_in[25];
    const float* bn2g = (const float*)d_in[26]; const float* bn2b = (const float*)d_in[27];
    const float* bn2m = (const float*)d_in[28]; const float* bn2v = (const float*)d_in[29];

    __half *xq, *xr, *q, *kv, *vt, *ctx, *h, *w;
    float *x1;
    cudaGetSymbolAddress((void**)&xq,  g_xq);
    cudaGetSymbolAddress((void**)&xr,  g_xr);
    cudaGetSymbolAddress((void**)&q,   g_q);
    cudaGetSymbolAddress((void**)&kv,  g_kv);
    cudaGetSymbolAddress((void**)&vt,  g_vt);
    cudaGetSymbolAddress((void**)&ctx, g_ctx);
    cudaGetSymbolAddress((void**)&x1,  g_x1);
    cudaGetSymbolAddress((void**)&h,   g_h);
    cudaGetSymbolAddress((void**)&w,   g_w);

    __half* cWq = w;
    __half* cWk = w + 1*1024*1024;     // cWk..cWv contiguous = fused KV weight
    __half* cWv = w + 2*1024*1024;
    __half* cWo = w + 3*1024*1024;
    __half* cW1 = w + 4*1024*1024;
    __half* cW2 = w + 8*1024*1024;

    float* outx = (float*)d_out;                    // [B,S,D]
    float* outa = outx + (long)NTOK * DD;           // [B,H,S,S]

    constexpr int SM_B   = 4 * (128*80 + 256*80);                       // 122880 B
    constexpr int SM_SF3 = 64*144 + 2*128*144 + 2*64*272 + 1536 + 4096; // 86528 B

    //                 BM  BN  WM WN ST  MODE OUTH
    auto* kP  = gemm_h<128,256,64,64,4,  0,   true >;  // q / kv -> half
    auto* kR  = gemm_h<128,256,64,64,4,  1,   false>;  // O-proj / W2 -> fp32
    auto* kG  = gemm_h<128,256,64,64,4,  2,   true >;  // W1 -> h half
    cudaFuncSetAttribute((const void*)kP,  cudaFuncAttributeMaxDynamicSharedMemorySize, SM_B);
    cudaFuncSetAttribute((const void*)kR,  cudaFuncAttributeMaxDynamicSharedMemorySize, SM_B);
    cudaFuncSetAttribute((const void*)kG,  cudaFuncAttributeMaxDynamicSharedMemorySize, SM_B);
    cudaFuncSetAttribute((const void*)sf3_k, cudaFuncAttributeMaxDynamicSharedMemorySize, SM_SF3);

    // 0) convert weights + x to half
    cvt_k<<<(1024*1024/4 + 255)/256, 256>>>(Wq, cWq, 1024*1024/4);
    cvt_k<<<(1024*1024/4 + 255)/256, 256>>>(Wk, cWk, 1024*1024/4);
    cvt_k<<<(1024*1024/4 + 255)/256, 256>>>(Wv, cWv, 1024*1024/4);
    cvt_k<<<(1024*1024/4 + 255)/256, 256>>>(Wo, cWo, 1024*1024/4);
    cvt_k<<<(4*1024*1024/4 + 255)/256, 256>>>(W1, cW1, 4*1024*1024/4);
    cvt_k<<<(4*1024*1024/4 + 255)/256, 256>>>(W2, cW2, 4*1024*1024/4);
    cvt_k<<<(NTOK*DD/4 + 255)/256, 256>>>(x, xr, NTOK*DD/4);

    // 1) pre-LN for query path (half out)
    ln_k<<<NTOK, 256>>>(x, lag, lab, xq);

    // 2) q projection (N=1024) + fused kv projection (N=2048)
    dim3 gQ(DD / 256, NTOK / 128, 1);
    kP<<<gQ, 256, SM_B>>>(xq, DD, cWq, DD, q, DD, DD,
        bq, nullptr, nullptr,0, nullptr,nullptr,nullptr,nullptr);
    dim3 gKV(2048 / 256, NTOK / 128, 1);
    kP<<<gKV, 256, SM_B>>>(xr, DD, cWk, DD, kv, 2048, DD,
        bk, bv, nullptr,0, nullptr,nullptr,nullptr,nullptr);

    // 2b) transpose V part of kv: [s, dk] -> [dk, s] per (b,h)
    dim3 gV(SS / 64, 1, BB * HH);
    vt_k<<<gV, 256>>>(kv + 1024, 2048, vt);

    // 3-5) fused scores + mask + softmax + attn@V (flash, two-pass)
    dim3 gSF(SS / 64, 1, BB * HH);
    sf3_k<<<gSF, 256, SM_SF3>>>(q, kv, vt, outa, ctx, mask);

    // 6) O projection + residual(x) + bn1 -> x1 (fp32)
    dim3 gO(DD / 256, NTOK / 128, 1);
    kR<<<gO, 256, SM_B>>>(ctx, DD, cWo, DD, x1, DD, DD,
        bo, nullptr, x, DD, bn1g,bn1b,bn1m,bn1v);

    // 7) FFN pre-LN (half out)
    ln_k<<<NTOK, 256>>>(x1, lfg, lfb, xq);

    // 8) h = bnff(gelu(xn W1^T + b1)) -> half  M=8192 N=4096 K=1024
    dim3 g1(DF / 256, NTOK / 128, 1);
    kG<<<g1, 256, SM_B>>>(xq, DD, cW1, DD, h, DF, DD,
        b1, nullptr, nullptr,0, bnffg,bnffb,bnffm,bnffv);

    // 9) out_x = bn2(h W2^T + b2 + x1)  M=8192 N=1024 K=4096
    dim3 g2(DD / 256, NTOK / 128, 1);
    kR<<<g2, 256, SM_B>>>(h, DF, cW2, DF, outx, DD, DF,
        b2, nullptr, x1, DD, bn2g,bn2b,bn2m,bn2v);
}

// round 16
// speedup vs baseline: 1.1491x; 1.0271x over previous
#include <cuda_runtime.h>
#include <cuda_fp16.h>
#include <math.h>
#include <stdint.h>

#define BB   8
#define SS   1024
#define DD   1024
#define HH   16
#define DKK  64
#define DF   4096
#define NTOK (BB*SS)        // 8192 tokens

// ---------------- scratch (static device globals; no allocation) ------------
__device__ __half g_xq[NTOK*DD];       // LN output (half), both LNs
__device__ __half g_xr[NTOK*DD];       // x as half
__device__ __half g_q [NTOK*DD];
__device__ __half g_kv[NTOK*2048];     // fused K|V
__device__ __half g_vt[NTOK*DD];       // [b,h][dk][token] transposed V
__device__ __half g_ctx[NTOK*DD];
__device__ float  g_x1[NTOK*DD];       // after bn1 (exact fp32)
__device__ __half g_h [NTOK*DF];       // FFN hidden
__device__ __half g_w [12*1024*1024];  // half weights: Wq Wk Wv Wo | W1 | W2

// ---------------- helpers ----------------------------------------------------
__device__ __forceinline__ void cpa16(void* s, const void* g) {
    unsigned sa = (unsigned)__cvta_generic_to_shared(s);
    asm volatile("cp.async.cg.shared.global [%0], [%1], 16;" :: "r"(sa), "l"(g));
}
__device__ __forceinline__ void cpa16u(uint32_t sa, const void* g) {
    asm volatile("cp.async.cg.shared.global [%0], [%1], 16;" :: "r"(sa), "l"(g));
}
__device__ __forceinline__ void cp_commit() { asm volatile("cp.async.commit_group;"); }
template<int N> __device__ __forceinline__ void cp_wait() {
    asm volatile("cp.async.wait_group %0;" :: "n"(N));
}
__device__ __forceinline__ void mma16(float* c, const unsigned* a, const unsigned* b) {
    asm volatile(
        "mma.sync.aligned.m16n8k16.row.col.f32.f16.f16.f32 "
        "{%0,%1,%2,%3}, {%4,%5,%6,%7}, {%8,%9}, {%0,%1,%2,%3};"
        : "+f"(c[0]), "+f"(c[1]), "+f"(c[2]), "+f"(c[3])
        : "r"(a[0]), "r"(a[1]), "r"(a[2]), "r"(a[3]), "r"(b[0]), "r"(b[1]));
}
__device__ __forceinline__ void ldm4(unsigned* r, uint32_t addr) {
    asm volatile("ldmatrix.sync.aligned.m8n8.x4.shared.b16 {%0,%1,%2,%3}, [%4];"
                 : "=r"(r[0]), "=r"(r[1]), "=r"(r[2]), "=r"(r[3]) : "r"(addr));
}
__device__ __forceinline__ unsigned packh2(float lo, float hi) {
    __half2 h = __floats2half2_rn(lo, hi);
    return *reinterpret_cast<unsigned*>(&h);
}
__device__ __forceinline__ float ex2f(float x) {
    float r;
    asm("ex2.approx.f32 %0, %1;" : "=f"(r) : "f"(x));
    return r;
}

// ---------------- fp16 tensor-core GEMM (ST-stage cp.async + ldmatrix, NT) ---
// MODE: 1 bias+res+BN | 2 bias+GELU+BN
template<int BM,int BN,int WM,int WN,int ST,int MODE,bool OUTH>
__global__ void __launch_bounds__(256)
gemm_h(const __half* __restrict__ A, int lda,
       const __half* __restrict__ B, int ldb,
       void* __restrict__ Cv, int ldc,
       int K,
       const float* __restrict__ bias,
       const float* __restrict__ res, int ldres,
       const float* __restrict__ bng, const float* __restrict__ bnb,
       const float* __restrict__ bnm, const float* __restrict__ bnv)
{
    constexpr int BK  = 32;
    constexpr int ASZ = BM * 80;
    constexpr int BSZ = BN * 80;

    extern __shared__ char smem[];
    const uint32_t smem_u = (uint32_t)__cvta_generic_to_shared(smem);

    const int tid = threadIdx.x;
    const int m0  = blockIdx.y * BM;
    const int n0  = blockIdx.x * BN;

    const int warp = tid >> 5, lane = tid & 31;
    constexpr int WGN = BN / WN;
    const int wm = warp / WGN, wn = warp % WGN;
    const int g  = lane >> 2,  t  = lane & 3;
    constexpr int MT  = WM / 16;
    constexpr int NTL = WN / 8;

    const int arow  = (lane & 7) | (((lane >> 3) & 1) << 3);
    const int akofs = (lane >> 4) << 3;
    const int brow  = ((lane >> 4) << 3) | (lane & 7);
    const int bkofs = ((lane >> 3) & 1) << 3;
    uint32_t aoff[MT], boff[NTL/2];
    #pragma unroll
    for (int mt = 0; mt < MT; mt++)
        aoff[mt] = ((wm * WM + mt * 16 + arow) * 40 + akofs) * 2;
    #pragma unroll
    for (int p = 0; p < NTL/2; p++)
        boff[p] = ((wn * WN + p * 16 + brow) * 40 + bkofs) * 2;

    float c[MT][NTL][4];
    #pragma unroll
    for (int i = 0; i < MT; i++)
        #pragma unroll
        for (int j = 0; j < NTL; j++)
            #pragma unroll
            for (int e = 0; e < 4; e++) c[i][j][e] = 0.0f;

    const int iters = K / BK;

    auto load_stage = [&](int it, int buf) {
        const int k0 = it * BK;
        char* dA = smem + buf * ASZ;
        char* dB = smem + ST * ASZ + buf * BSZ;
        #pragma unroll
        for (int s = tid; s < BM * 4; s += 256) {
            int row = s >> 2, seg = s & 3;
            cpa16(dA + row * 80 + seg * 16,
                  A + (long)(m0 + row) * lda + k0 + seg * 8);
        }
        #pragma unroll
        for (int s = tid; s < BN * 4; s += 256) {
            int row = s >> 2, seg = s & 3;
            cpa16(dB + row * 80 + seg * 16,
                  B + (long)(n0 + row) * ldb + k0 + seg * 8);
        }
    };

    #pragma unroll
    for (int s = 0; s < ST - 1; s++) {
        if (s < iters) load_stage(s, s);
        cp_commit();
    }

    for (int it = 0; it < iters; ++it) {
        cp_wait<ST - 2>();
        __syncthreads();

        if (it + ST - 1 < iters) load_stage(it + ST - 1, (it + ST - 1) % ST);
        cp_commit();

        const int buf = it % ST;
        const uint32_t aBase = smem_u + buf * ASZ;
        const uint32_t bBase = smem_u + ST * ASZ + buf * BSZ;

        #pragma unroll
        for (int ks = 0; ks < BK; ks += 16) {
            unsigned a[MT][4], b[NTL/2][4];
            #pragma unroll
            for (int mt = 0; mt < MT; mt++)
                ldm4(a[mt], aBase + aoff[mt] + ks * 2);
            #pragma unroll
            for (int p = 0; p < NTL/2; p++)
                ldm4(b[p], bBase + boff[p] + ks * 2);
            #pragma unroll
            for (int mt = 0; mt < MT; mt++)
                #pragma unroll
                for (int p = 0; p < NTL/2; p++) {
                    mma16(c[mt][2*p],   a[mt], &b[p][0]);
                    mma16(c[mt][2*p+1], a[mt], &b[p][2]);
                }
        }
    }

    auto ep = [&](float v, int n, long m) -> float {
        if constexpr (MODE == 1) {
            v += bias[n] + res[m * ldres + n];
            v = (v - bnm[n]) * rsqrtf(bnv[n] + 1e-5f) * bng[n] + bnb[n];
        } else if constexpr (MODE == 2) {
            v += bias[n];
            v = 0.5f * v * (1.0f + erff(v * 0.70710678118654752f));
            v = (v - bnm[n]) * rsqrtf(bnv[n] + 1e-5f) * bng[n] + bnb[n];
        }
        return v;
    };

    #pragma unroll
    for (int mt = 0; mt < MT; mt++) {
        #pragma unroll
        for (int nt = 0; nt < NTL; nt++) {
            const int row = m0 + wm * WM + mt * 16 + g;
            const int col = n0 + wn * WN + nt * 8 + 2 * t;
            float v00 = ep(c[mt][nt][0], col,     row);
            float v01 = ep(c[mt][nt][1], col + 1, row);
            float v10 = ep(c[mt][nt][2], col,     row + 8);
            float v11 = ep(c[mt][nt][3], col + 1, row + 8);
            if constexpr (OUTH) {
                __half* Ch = (__half*)Cv;
                *(__half2*)(Ch + (long)(row    ) * ldc + col) = __floats2half2_rn(v00, v01);
                *(__half2*)(Ch + (long)(row + 8) * ldc + col) = __floats2half2_rn(v10, v11);
            } else {
                float* Cf = (float*)Cv;
                *(float2*)(Cf + (long)(row    ) * ldc + col) = make_float2(v00, v01);
                *(float2*)(Cf + (long)(row + 8) * ldc + col) = make_float2(v10, v11);
            }
        }
    }
}

// ---------------- fused Q+KV projection GEMM (N=3072, per-block A/C select) --
// cols [0,1024): A=xq, C=q (ldc 1024), bias bq
// cols [1024,2048): A=xr, C=kv (ldc 2048, col-1024), bias bk
// cols [2048,3072): A=xr, C=kv (col-1024), bias bv
__global__ void __launch_bounds__(256)
gemm_qkv(const __half* __restrict__ Aq, const __half* __restrict__ Ax,
         const __half* __restrict__ W,          // fused [3072, 1024] K-major
         __half* __restrict__ qp, __half* __restrict__ kvp,
         const float* __restrict__ bq, const float* __restrict__ bk,
         const float* __restrict__ bv)
{
    constexpr int BM = 128, BN = 256, WM = 64, WN = 64, ST = 4, BK = 32;
    constexpr int ASZ = BM * 80;
    constexpr int BSZ = BN * 80;
    constexpr int K = 1024;

    extern __shared__ char smem[];
    const uint32_t smem_u = (uint32_t)__cvta_generic_to_shared(smem);

    const int tid = threadIdx.x;
    const int m0  = blockIdx.y * BM;
    const int n0  = blockIdx.x * BN;

    const bool isQ = (n0 < 1024);
    const __half* A = isQ ? Aq : Ax;
    __half* Cp  = isQ ? qp : kvp;
    const int ldcs = isQ ? 1024 : 2048;
    const int csub = isQ ? 0 : 1024;
    const float* bp = isQ ? bq : ((n0 < 2048) ? bk : bv);
    const int bsub  = isQ ? 0 : ((n0 < 2048) ? 1024 : 2048);

    const int warp = tid >> 5, lane = tid & 31;
    const int wm = warp >> 2, wn = warp & 3;   // WGN = 4
    const int g  = lane >> 2,  t  = lane & 3;
    constexpr int MT  = WM / 16;   // 4
    constexpr int NTL = WN / 8;    // 8

    const int arow  = (lane & 7) | (((lane >> 3) & 1) << 3);
    const int akofs = (lane >> 4) << 3;
    const int brow  = ((lane >> 4) << 3) | (lane & 7);
    const int bkofs = ((lane >> 3) & 1) << 3;
    uint32_t aoff[MT], boff[NTL/2];
    #pragma unroll
    for (int mt = 0; mt < MT; mt++)
        aoff[mt] = ((wm * WM + mt * 16 + arow) * 40 + akofs) * 2;
    #pragma unroll
    for (int p = 0; p < NTL/2; p++)
        boff[p] = ((wn * WN + p * 16 + brow) * 40 + bkofs) * 2;

    float c[MT][NTL][4];
    #pragma unroll
    for (int i = 0; i < MT; i++)
        #pragma unroll
        for (int j = 0; j < NTL; j++)
            #pragma unroll
            for (int e = 0; e < 4; e++) c[i][j][e] = 0.0f;

    const int iters = K / BK;

    auto load_stage = [&](int it, int buf) {
        const int k0 = it * BK;
        char* dA = smem + buf * ASZ;
        char* dB = smem + ST * ASZ + buf * BSZ;
        #pragma unroll
        for (int s = tid; s < BM * 4; s += 256) {
            int row = s >> 2, seg = s & 3;
            cpa16(dA + row * 80 + seg * 16,
                  A + (long)(m0 + row) * 1024 + k0 + seg * 8);
        }
        #pragma unroll
        for (int s = tid; s < BN * 4; s += 256) {
            int row = s >> 2, seg = s & 3;
            cpa16(dB + row * 80 + seg * 16,
                  W + (long)(n0 + row) * 1024 + k0 + seg * 8);
        }
    };

    #pragma unroll
    for (int s = 0; s < ST - 1; s++) {
        if (s < iters) load_stage(s, s);
        cp_commit();
    }

    for (int it = 0; it < iters; ++it) {
        cp_wait<ST - 2>();
        __syncthreads();

        if (it + ST - 1 < iters) load_stage(it + ST - 1, (it + ST - 1) % ST);
        cp_commit();

        const int buf = it % ST;
        const uint32_t aBase = smem_u + buf * ASZ;
        const uint32_t bBase = smem_u + ST * ASZ + buf * BSZ;

        #pragma unroll
        for (int ks = 0; ks < BK; ks += 16) {
            unsigned a[MT][4], b[NTL/2][4];
            #pragma unroll
            for (int mt = 0; mt < MT; mt++)
                ldm4(a[mt], aBase + aoff[mt] + ks * 2);
            #pragma unroll
            for (int p = 0; p < NTL/2; p++)
                ldm4(b[p], bBase + boff[p] + ks * 2);
            #pragma unroll
            for (int mt = 0; mt < MT; mt++)
                #pragma unroll
                for (int p = 0; p < NTL/2; p++) {
                    mma16(c[mt][2*p],   a[mt], &b[p][0]);
                    mma16(c[mt][2*p+1], a[mt], &b[p][2]);
                }
        }
    }

    #pragma unroll
    for (int mt = 0; mt < MT; mt++) {
        #pragma unroll
        for (int nt = 0; nt < NTL; nt++) {
            const int row = m0 + wm * WM + mt * 16 + g;
            const int col = n0 + wn * WN + nt * 8 + 2 * t;
            float v00 = c[mt][nt][0] + bp[col     - bsub];
            float v01 = c[mt][nt][1] + bp[col + 1 - bsub];
            float v10 = c[mt][nt][2] + bp[col     - bsub];
            float v11 = c[mt][nt][3] + bp[col + 1 - bsub];
            const int cc = col - csub;
            *(__half2*)(Cp + (long)(row    ) * ldcs + cc) = __floats2half2_rn(v00, v01);
            *(__half2*)(Cp + (long)(row + 8) * ldcs + cc) = __floats2half2_rn(v10, v11);
        }
    }
}

// ---------------- fused flash attention: scores+mask+softmax+attn@V ----------
__global__ void __launch_bounds__(256)
sf3_k(const __half* __restrict__ q,
      const __half* __restrict__ kv,
      const __half* __restrict__ vt,
      float* __restrict__ outa,
      __half* __restrict__ ctx,
      const int* __restrict__ mask)
{
    constexpr int ROWS = 64;
    constexpr int QSZ  = ROWS * 144;
    constexpr int KSZ  = 128 * 144;
    constexpr int VSZ  = 64 * 272;
    constexpr float SCL = 0.18033688011112042f;   // 0.125 * log2(e)

    extern __shared__ char smem[];
    const uint32_t smem_u = (uint32_t)__cvta_generic_to_shared(smem);
    const uint32_t qBase = smem_u;
    const uint32_t kBase = smem_u + QSZ;
    const uint32_t vBase = smem_u + QSZ + 2 * KSZ;
    float* sM   = (float*)(smem + QSZ + 2 * KSZ + 2 * VSZ);
    float* sSm  = sM + 128;
    float* fM   = sSm + 128;
    float* fI   = fM + 64;
    float* madd = fI + 64;
    float* xch  = (float*)(smem + QSZ + 2 * KSZ);

    const int z  = blockIdx.z;
    const int zb = z >> 4;
    const int zh = z & 15;
    const int m0r = blockIdx.x * ROWS;

    const int tid = threadIdx.x;
    const int warp = tid >> 5, lane = tid & 31;
    const int wm = warp >> 1, wn = warp & 1;
    const int g  = lane >> 2,  t = lane & 3;

    const int arow  = (lane & 7) | (((lane >> 3) & 1) << 3);
    const int akofs = (lane >> 4) << 3;
    const int brow  = ((lane >> 4) << 3) | (lane & 7);
    const int bkofs = ((lane >> 3) & 1) << 3;
    const uint32_t aoff = ((wm * 16 + arow) * 72 + akofs) * 2;
    uint32_t boff[4], vboff[4];
    #pragma unroll
    for (int p = 0; p < 4; p++) {
        boff[p]  = ((wn * 64 + p * 16 + brow) * 72 + bkofs) * 2;
        vboff[p] = ((p * 16 + brow) * 136 + bkofs) * 2;
    }

    auto load_stage = [&](int it) {
        const int nc = it & 7;
        const int buf = it & 1;
        #pragma unroll
        for (int s = tid; s < 1024; s += 256) {
            int row = s >> 3, seg = s & 7;
            cpa16u(kBase + buf * KSZ + row * 144 + seg * 16,
                   kv + (long)(zb * SS + nc * 128 + row) * 2048 + zh * 64 + seg * 8);
        }
        if (it >= 8) {
            #pragma unroll
            for (int s = tid; s < 1024; s += 256) {
                int row = s >> 4, seg = s & 15;
                cpa16u(vBase + buf * VSZ + row * 272 + seg * 16,
                       vt + ((long)z * 64 + row) * SS + nc * 128 + seg * 8);
            }
        }
    };

    #pragma unroll
    for (int s = tid; s < ROWS * 8; s += 256) {
        int row = s >> 3, seg = s & 7;
        cpa16u(qBase + row * 144 + seg * 16,
               q + (long)(zb * SS + m0r + row) * DD + zh * 64 + seg * 8);
    }
    #pragma unroll
    for (int s = tid; s < 1024; s += 256)
        madd[s] = mask[zb * SS + s] ? 0.0f : -1.4426950e9f;
    load_stage(0);
    cp_commit();

    float mrun0 = -1e30f, mrun1 = -1e30f, srun0 = 0.0f, srun1 = 0.0f;
    float ctxacc[8][4];
    #pragma unroll
    for (int j = 0; j < 8; j++)
        #pragma unroll
        for (int e = 0; e < 4; e++) ctxacc[j][e] = 0.0f;
    const long zbase = (long)z * SS * SS;

    for (int it = 0; it < 16; ++it) {
        const int nc = it & 7;
        if (it + 1 < 16) load_stage(it + 1);
        cp_commit();
        cp_wait<1>();
        __syncthreads();

        if (it == 8) {
            if (t == 0) {
                const int r0 = wm * 16 + g;
                sM [r0 * 2 + wn] = mrun0;  sSm[r0 * 2 + wn] = srun0;
                sM [(r0+8) * 2 + wn] = mrun1;  sSm[(r0+8) * 2 + wn] = srun1;
            }
            __syncthreads();
            if (tid < 64) {
                float m = fmaxf(sM[tid*2], sM[tid*2+1]);
                float s = sSm[tid*2]   * ex2f(sM[tid*2]   - m)
                        + sSm[tid*2+1] * ex2f(sM[tid*2+1] - m);
                fM[tid] = m; fI[tid] = 1.0f / s;
            }
            __syncthreads();
        }

        const uint32_t kb = kBase + (it & 1) * KSZ;
        float c[8][4];
        #pragma unroll
        for (int i = 0; i < 8; i++)
            #pragma unroll
            for (int e = 0; e < 4; e++) c[i][e] = 0.0f;

        #pragma unroll
        for (int ks = 0; ks < 64; ks += 16) {
            unsigned a[4], b[4][4];
            ldm4(a, qBase + aoff + ks * 2);
            #pragma unroll
            for (int p = 0; p < 4; p++)
                ldm4(b[p], kb + boff[p] + ks * 2);
            #pragma unroll
            for (int p = 0; p < 4; p++) {
                mma16(c[2*p],   a, &b[p][0]);
                mma16(c[2*p+1], a, &b[p][2]);
            }
        }

        #pragma unroll
        for (int j = 0; j < 8; j++) {
            const int col = nc * 128 + wn * 64 + j * 8 + 2 * t;
            const float mA = madd[col], mB = madd[col + 1];
            c[j][0] = fmaf(c[j][0], SCL, mA);
            c[j][1] = fmaf(c[j][1], SCL, mB);
            c[j][2] = fmaf(c[j][2], SCL, mA);
            c[j][3] = fmaf(c[j][3], SCL, mB);
        }

        if (it < 8) {
            float m0c = -1e30f, m1c = -1e30f;
            #pragma unroll
            for (int j = 0; j < 8; j++) {
                m0c = fmaxf(m0c, fmaxf(c[j][0], c[j][1]));
                m1c = fmaxf(m1c, fmaxf(c[j][2], c[j][3]));
            }
            #pragma unroll
            for (int o = 1; o <= 2; o <<= 1) {
                m0c = fmaxf(m0c, __shfl_xor_sync(0xffffffffu, m0c, o));
                m1c = fmaxf(m1c, __shfl_xor_sync(0xffffffffu, m1c, o));
            }
            const float n0 = fmaxf(mrun0, m0c), n1 = fmaxf(mrun1, m1c);
            float s0 = 0.0f, s1 = 0.0f;
            #pragma unroll
            for (int j = 0; j < 8; j++) {
                s0 += ex2f(c[j][0] - n0) + ex2f(c[j][1] - n0);
                s1 += ex2f(c[j][2] - n1) + ex2f(c[j][3] - n1);
            }
            #pragma unroll
            for (int o = 1; o <= 2; o <<= 1) {
                s0 += __shfl_xor_sync(0xffffffffu, s0, o);
                s1 += __shfl_xor_sync(0xffffffffu, s1, o);
            }
            srun0 = srun0 * ex2f(mrun0 - n0) + s0; mrun0 = n0;
            srun1 = srun1 * ex2f(mrun1 - n1) + s1; mrun1 = n1;
        } else {
            const int r0 = wm * 16 + g, r1 = r0 + 8;
            const float fm0 = fM[r0], fi0 = fI[r0];
            const float fm1 = fM[r1], fi1 = fI[r1];
            const long b0r = zbase + (long)(m0r + r0) * SS;
            const long b1r = zbase + (long)(m0r + r1) * SS;
            unsigned wv[8][2];
            #pragma unroll
            for (int j = 0; j < 8; j++) {
                const int col = nc * 128 + wn * 64 + j * 8 + 2 * t;
                float w00 = ex2f(c[j][0] - fm0) * fi0;
                float w01 = ex2f(c[j][1] - fm0) * fi0;
                float w10 = ex2f(c[j][2] - fm1) * fi1;
                float w11 = ex2f(c[j][3] - fm1) * fi1;
                __stcs((float2*)&outa[b0r + col], make_float2(w00, w01));
                __stcs((float2*)&outa[b1r + col], make_float2(w10, w11));
                wv[j][0] = packh2(w00, w01);
                wv[j][1] = packh2(w10, w11);
            }
            const uint32_t vb = vBase + (it & 1) * VSZ;
            const uint32_t vkofs = (uint32_t)(wn * 64) * 2;
            #pragma unroll
            for (int s = 0; s < 4; s++) {
                unsigned a[4] = { wv[2*s][0], wv[2*s][1], wv[2*s+1][0], wv[2*s+1][1] };
                #pragma unroll
                for (int p = 0; p < 4; p++) {
                    unsigned bv[4];
                    ldm4(bv, vb + vboff[p] + vkofs + s * 32);
                    mma16(ctxacc[2*p],   a, &bv[0]);
                    mma16(ctxacc[2*p+1], a, &bv[2]);
                }
            }
        }
        __syncthreads();
    }

    if (wn == 1) {
        float* dst = xch + (wm * 32 + lane) * 32;
        #pragma unroll
        for (int j = 0; j < 8; j++)
            #pragma unroll
            for (int e = 0; e < 4; e++) dst[j * 4 + e] = ctxacc[j][e];
    }
    __syncthreads();
    if (wn == 0) {
        const float* src = xch + (wm * 32 + lane) * 32;
        const int r0 = m0r + wm * 16 + g, r1 = r0 + 8;
        #pragma unroll
        for (int j = 0; j < 8; j++) {
            float v0 = ctxacc[j][0] + src[j*4+0];
            float v1 = ctxacc[j][1] + src[j*4+1];
            float v2 = ctxacc[j][2] + src[j*4+2];
            float v3 = ctxacc[j][3] + src[j*4+3];
            const int dk = j * 8 + 2 * t;
            *(__half2*)(ctx + (long)(zb * SS + r0) * DD + zh * 64 + dk) = __floats2half2_rn(v0, v1);
            *(__half2*)(ctx + (long)(zb * SS + r1) * DD + zh * 64 + dk) = __floats2half2_rn(v2, v3);
        }
    }
}

// ---------------- fused weight conversion: all six weights in one kernel -----
// dst g_w is contiguous; source selected by block-uniform range on f4 index.
__global__ void __launch_bounds__(256)
cvtw_k(const float* __restrict__ Wq, const float* __restrict__ Wk,
       const float* __restrict__ Wv, const float* __restrict__ Wo,
       const float* __restrict__ W1, const float* __restrict__ W2,
       __half* __restrict__ out)
{
    const int i = blockIdx.x * 256 + threadIdx.x;     // f4 group index (0..3145727)
    const float* src;
    int off;
    if      (i <  262144) { src = Wq; off = i; }
    else if (i <  524288) { src = Wk; off = i -  262144; }
    else if (i <  786432) { src = Wv; off = i -  524288; }
    else if (i < 1048576) { src = Wo; off = i -  786432; }
    else if (i < 2097152) { src = W1; off = i - 1048576; }
    else                  { src = W2; off = i - 2097152; }
    float4 v = ((const float4*)src)[off];
    ((__half2*)out)[2*i]   = __floats2half2_rn(v.x, v.y);
    ((__half2*)out)[2*i+1] = __floats2half2_rn(v.z, v.w);
}

// ---------------- V transpose: kv[token][1024+h*64+dk] -> vt[b,h][dk][s] -----
__global__ void __launch_bounds__(256)
vt_k(const __half* __restrict__ v, int ldv, __half* __restrict__ vt)
{
    __shared__ __half tile[64][72];
    const int z = blockIdx.z;
    const int b = z >> 4, h = z & 15;
    const int s0 = blockIdx.x * 64;
    const int tid = threadIdx.x;

    #pragma unroll
    for (int p = 0; p < 2; p++) {
        int r   = p * 32 + (tid >> 3);
        int seg = tid & 7;
        uint4 d = *(const uint4*)(v + ((long)(b * SS + s0 + r)) * ldv + h * 64 + seg * 8);
        *(uint4*)&tile[r][seg * 8] = d;
    }
    __syncthreads();
    #pragma unroll
    for (int p = 0; p < 2; p++) {
        int c   = p * 32 + (tid >> 3);
        int seg = tid & 7;
        __half tmp[8];
        #pragma unroll
        for (int j = 0; j < 8; j++) tmp[j] = tile[seg * 8 + j][c];
        *(uint4*)(vt + ((long)z * 64 + c) * SS + s0 + seg * 8) = *(uint4*)tmp;
    }
}

// ---------------- LayerNorm over D=1024; half output (+optional raw copy) ---
template<bool CVT>
__global__ void __launch_bounds__(256)
ln_k(const float* __restrict__ x, const float* __restrict__ g,
     const float* __restrict__ b, __half* __restrict__ o,
     __half* __restrict__ oraw)
{
    __shared__ float red[8];
    const long row = blockIdx.x;
    const int  t = threadIdx.x, lane = t & 31, w = t >> 5;

    float4 v = ((const float4*)(x + row * DD))[t];
    if constexpr (CVT) {
        __half2* rp = (__half2*)(oraw + row * DD);
        rp[2*t]   = __floats2half2_rn(v.x, v.y);
        rp[2*t+1] = __floats2half2_rn(v.z, v.w);
    }
    float s = v.x + v.y + v.z + v.w;
    #pragma unroll
    for (int off = 16; off; off >>= 1) s += __shfl_down_sync(0xffffffffu, s, off);
    if (!lane) red[w] = s;
    __syncthreads();
    if (t == 0) { float a = 0.f; for (int i = 0; i < 8; i++) a += red[i]; red[0] = a; }
    __syncthreads();
    const float mu = red[0] * (1.0f / DD);
    __syncthreads();

    float d0 = v.x - mu, d1 = v.y - mu, d2 = v.z - mu, d3 = v.w - mu;
    float sq = d0*d0 + d1*d1 + d2*d2 + d3*d3;
    #pragma unroll
    for (int off = 16; off; off >>= 1) sq += __shfl_down_sync(0xffffffffu, sq, off);
    if (!lane) red[w] = sq;
    __syncthreads();
    if (t == 0) { float a = 0.f; for (int i = 0; i < 8; i++) a += red[i]; red[0] = a; }
    __syncthreads();
    const float rs = rsqrtf(red[0] * (1.0f / DD) + 1e-5f);

    float4 g4 = ((const float4*)g)[t];
    float4 b4 = ((const float4*)b)[t];
    __half2* op = (__half2*)(o + row * DD);
    op[2*t]   = __floats2half2_rn(d0 * rs * g4.x + b4.x, d1 * rs * g4.y + b4.y);
    op[2*t+1] = __floats2half2_rn(d2 * rs * g4.z + b4.z, d3 * rs * g4.w + b4.w);
}

// ---------------- host orchestration ----------------------------------------
extern "C" void kernel_launch(void* const* d_in, const int* in_sizes, int n_in,
                              void* d_out, int out_size)
{
    const float* x    = (const float*)d_in[0];
    const int*   mask = (const int*)  d_in[1];
    const float* Wq = (const float*)d_in[2];  const float* bq = (const float*)d_in[3];
    const float* Wk = (const float*)d_in[4];  const float* bk = (const float*)d_in[5];
    const float* Wv = (const float*)d_in[6];  const float* bv = (const float*)d_in[7];
    const float* Wo = (const float*)d_in[8];  const float* bo = (const float*)d_in[9];
    const float* lag = (const float*)d_in[10]; const float* lab = (const float*)d_in[11];
    const float* W1 = (const float*)d_in[12]; const float* b1 = (const float*)d_in[13];
    const float* W2 = (const float*)d_in[14]; const float* b2 = (const float*)d_in[15];
    const float* lfg = (const float*)d_in[16]; const float* lfb = (const float*)d_in[17];
    const float* bnffg = (const float*)d_in[18]; const float* bnffb = (const float*)d_in[19];
    const float* bnffm = (const float*)d_in[20]; const float* bnffv = (const float*)d_in[21];
    const float* bn1g = (const float*)d_in[22]; const float* bn1b = (const float*)d_in[23];
    const float* bn1m = (const float*)d_in[24]; const float* bn1v = (const float*)d_in[25];
    const float* bn2g = (const float*)d_in[26]; const float* bn2b = (const float*)d_in[27];
    const float* bn2m = (const float*)d_in[28]; const float* bn2v = (const float*)d_in[29];

    __half *xq, *xr, *q, *kv, *vt, *ctx, *h, *w;
    float *x1;
    cudaGetSymbolAddress((void**)&xq,  g_xq);
    cudaGetSymbolAddress((void**)&xr,  g_xr);
    cudaGetSymbolAddress((void**)&q,   g_q);
    cudaGetSymbolAddress((void**)&kv,  g_kv);
    cudaGetSymbolAddress((void**)&vt,  g_vt);
    cudaGetSymbolAddress((void**)&ctx, g_ctx);
    cudaGetSymbolAddress((void**)&x1,  g_x1);
    cudaGetSymbolAddress((void**)&h,   g_h);
    cudaGetSymbolAddress((void**)&w,   g_w);

    __half* cWqkv = w;                 // fused [3072, 1024]
    __half* cWo = w + 3*1024*1024;
    __half* cW1 = w + 4*1024*1024;
    __half* cW2 = w + 8*1024*1024;

    float* outx = (float*)d_out;                    // [B,S,D]
    float* outa = outx + (long)NTOK * DD;           // [B,H,S,S]

    constexpr int SM_B   = 4 * (128*80 + 256*80);                       // 122880 B
    constexpr int SM_SF3 = 64*144 + 2*128*144 + 2*64*272 + 1536 + 4096; // 86528 B

    //                 BM  BN  WM WN ST  MODE OUTH
    auto* kR  = gemm_h<128,256,64,64,4,  1,   false>;  // O-proj / W2 -> fp32
    auto* kG  = gemm_h<128,256,64,64,4,  2,   true >;  // W1 -> h half
    cudaFuncSetAttribute((const void*)kR,  cudaFuncAttributeMaxDynamicSharedMemorySize, SM_B);
    cudaFuncSetAttribute((const void*)kG,  cudaFuncAttributeMaxDynamicSharedMemorySize, SM_B);
    cudaFuncSetAttribute((const void*)gemm_qkv, cudaFuncAttributeMaxDynamicSharedMemorySize, SM_B);
    cudaFuncSetAttribute((const void*)sf3_k, cudaFuncAttributeMaxDynamicSharedMemorySize, SM_SF3);

    // 0) convert all weights to half (one kernel; dst contiguous in g_w)
    cvtw_k<<<12288, 256>>>(Wq, Wk, Wv, Wo, W1, W2, w);

    // 1) pre-LN for query path + raw half copy of x (single pass over x)
    ln_k<true><<<NTOK, 256>>>(x, lag, lab, xq, xr);

    // 2) fused q + kv projection (N=3072, one launch)
    dim3 gQKV(3072 / 256, NTOK / 128, 1);
    gemm_qkv<<<gQKV, 256, SM_B>>>(xq, xr, cWqkv, q, kv, bq, bk, bv);

    // 2b) transpose V part of kv: [s, dk] -> [dk, s] per (b,h)
    dim3 gV(SS / 64, 1, BB * HH);
    vt_k<<<gV, 256>>>(kv + 1024, 2048, vt);

    // 3-5) fused scores + mask + softmax + attn@V (flash, two-pass)
    dim3 gSF(SS / 64, 1, BB * HH);
    sf3_k<<<gSF, 256, SM_SF3>>>(q, kv, vt, outa, ctx, mask);

    // 6) O projection + residual(x) + bn1 -> x1 (fp32)
    dim3 gO(DD / 256, NTOK / 128, 1);
    kR<<<gO, 256, SM_B>>>(ctx, DD, cWo, DD, x1, DD, DD,
        bo, x, DD, bn1g,bn1b,bn1m,bn1v);

    // 7) FFN pre-LN (half out, no raw copy)
    ln_k<false><<<NTOK, 256>>>(x1, lfg, lfb, xq, nullptr);

    // 8) h = bnff(gelu(xn W1^T + b1)) -> half  M=8192 N=4096 K=1024
    dim3 g1(DF / 256, NTOK / 128, 1);
    kG<<<g1, 256, SM_B>>>(xq, DD, cW1, DD, h, DF, DD,
        b1, nullptr, 0, bnffg,bnffb,bnffm,bnffv);

    // 9) out_x = bn2(h W2^T + b2 + x1)  M=8192 N=1024 K=4096
    dim3 g2(DD / 256, NTOK / 128, 1);
    kR<<<g2, 256, SM_B>>>(h, DF, cW2, DF, outx, DD, DF,
        b2, x1, DD, bn2g,bn2b,bn2m,bn2v);
}